// round 11
// baseline (speedup 1.0000x reference)
#include <cuda_runtime.h>
#include <cuda_bf16.h>
#include <math.h>
#include <stdint.h>

#define TT 4096
#define HH 1024
#define EE 8
#define FF 2048
#define CAP 4096
#define NW (EE * HH * FF)
#define ND (EE * FF * HH)

// ---------------- scratch ----------------
__device__ int   g_count[EE];
__device__ int   g_plist[EE * CAP];
__device__ float g_wpair[TT * 2];
__device__ __align__(16) __nv_bfloat16 g_xh[TT * HH], g_xl[TT * HH];
__device__ __align__(16) __nv_bfloat16 g_wuh[NW], g_wul[NW];
__device__ __align__(16) __nv_bfloat16 g_wgh[NW], g_wgl[NW];
__device__ __align__(16) __nv_bfloat16 g_wdh[ND], g_wdl[ND];
__device__ __align__(16) __nv_bfloat16 g_ih[(size_t)TT * 2 * FF], g_il[(size_t)TT * 2 * FF];
// stage2 partials: [kc][packed id][HH]  (every slot written exactly once -> no zeroing)
__device__ __align__(16) float g_part[(size_t)2 * TT * 2 * HH];   // 67 MB

// ---------------- helpers ----------------
__device__ __forceinline__ uint32_t smem_u32(const void* p) {
    uint32_t a;
    asm("{ .reg .u64 t; cvta.to.shared.u64 t, %1; cvt.u32.u64 %0, t; }" : "=r"(a) : "l"(p));
    return a;
}
__device__ __forceinline__ void splitf(float f, uint32_t& h, uint32_t& l) {
    __nv_bfloat16 hb = __float2bfloat16_rn(f);
    float rf = f - __bfloat162float(hb);
    __nv_bfloat16 lb = __float2bfloat16_rn(rf);
    h = (uint32_t)__bfloat16_as_ushort(hb);
    l = (uint32_t)__bfloat16_as_ushort(lb);
}

#define CP16(dst, src)  asm volatile("cp.async.cg.shared.global [%0], [%1], 16;" :: "r"(dst), "l"(src))
#define CPCOMMIT()      asm volatile("cp.async.commit_group;" ::: "memory")
#define CPWAIT1()       asm volatile("cp.async.wait_group 1;" ::: "memory")

#define LDSM4(r, a)                                                                   \
    asm volatile("ldmatrix.sync.aligned.m8n8.x4.shared.b16 {%0,%1,%2,%3}, [%4];"      \
        : "=r"((r)[0]), "=r"((r)[1]), "=r"((r)[2]), "=r"((r)[3]) : "r"(a))
#define LDSM4T(r, a)                                                                  \
    asm volatile("ldmatrix.sync.aligned.m8n8.x4.trans.shared.b16 {%0,%1,%2,%3}, [%4];"\
        : "=r"((r)[0]), "=r"((r)[1]), "=r"((r)[2]), "=r"((r)[3]) : "r"(a))

__device__ __forceinline__ void mma_bf16(float* d, const uint32_t* a, uint32_t b0, uint32_t b1) {
    asm volatile(
        "mma.sync.aligned.m16n8k16.row.col.f32.bf16.bf16.f32 "
        "{%0,%1,%2,%3},{%4,%5,%6,%7},{%8,%9},{%0,%1,%2,%3};"
        : "+f"(d[0]), "+f"(d[1]), "+f"(d[2]), "+f"(d[3])
        : "r"(a[0]), "r"(a[1]), "r"(a[2]), "r"(a[3]), "r"(b0), "r"(b1));
}

// ---------------- fused split prepass (also resets expert counters) ----------------
#define NW4 (NW / 4)
#define NX4 (TT * HH / 4)
__global__ __launch_bounds__(256) void split_all(const float4* __restrict__ wu,
                                                 const float4* __restrict__ wg,
                                                 const float4* __restrict__ wd,
                                                 const float4* __restrict__ x) {
    if (blockIdx.x == 0 && threadIdx.x < EE) g_count[threadIdx.x] = 0;
    int i = blockIdx.x * blockDim.x + threadIdx.x;
    const float4* src;
    __nv_bfloat16 *hp, *lp;
    int j;
    if (i < NW4)               { src = wu; hp = g_wuh; lp = g_wul; j = i; }
    else if (i < 2 * NW4)      { src = wg; hp = g_wgh; lp = g_wgl; j = i - NW4; }
    else if (i < 3 * NW4)      { src = wd; hp = g_wdh; lp = g_wdl; j = i - 2 * NW4; }
    else if (i < 3 * NW4 + NX4){ src = x;  hp = g_xh;  lp = g_xl;  j = i - 3 * NW4; }
    else return;
    float4 v = src[j];
    uint32_t h0, h1, h2, h3, l0, l1, l2, l3;
    splitf(v.x, h0, l0); splitf(v.y, h1, l1);
    splitf(v.z, h2, l2); splitf(v.w, h3, l3);
    ((uint2*)hp)[j] = make_uint2(h0 | (h1 << 16), h2 | (h3 << 16));
    ((uint2*)lp)[j] = make_uint2(l0 | (l1 << 16), l2 | (l3 << 16));
}

// ---------------- router ----------------
__global__ __launch_bounds__(128) void router_kernel(const float* __restrict__ x,
                                                     const float* __restrict__ gw) {
    int t = blockIdx.x, tid = threadIdx.x;
    const float* xp = x + (size_t)t * HH;
    double part[EE];
#pragma unroll
    for (int e = 0; e < EE; e++) part[e] = 0.0;
#pragma unroll
    for (int s = 0; s < HH / 128; s++) {
        int h = tid + s * 128;
        double xv = (double)xp[h];
#pragma unroll
        for (int e = 0; e < EE; e++) part[e] += xv * (double)gw[h * EE + e];
    }
    __shared__ double red[EE][128];
#pragma unroll
    for (int e = 0; e < EE; e++) red[e][tid] = part[e];
    __syncthreads();
    for (int st = 64; st > 0; st >>= 1) {
        if (tid < st) {
#pragma unroll
            for (int e = 0; e < EE; e++) red[e][tid] += red[e][tid + st];
        }
        __syncthreads();
    }
    if (tid == 0) {
        double l[EE];
#pragma unroll
        for (int e = 0; e < EE; e++) l[e] = red[e][0];
        int i0 = 0;
        for (int e = 1; e < EE; e++) if (l[e] > l[i0]) i0 = e;
        int i1 = (i0 == 0) ? 1 : 0;
        for (int e = 0; e < EE; e++) if (e != i0 && l[e] > l[i1]) i1 = e;
        double d  = exp(l[i1] - l[i0]);
        float  w0 = (float)(1.0 / (1.0 + d));
        float  w1 = (float)(d / (1.0 + d));
        int p0 = atomicAdd(&g_count[i0], 1);
        g_plist[i0 * CAP + p0] = t * 2;
        int p1 = atomicAdd(&g_count[i1], 1);
        g_plist[i1 * CAP + p1] = t * 2 + 1;
        g_wpair[t * 2]     = w0;
        g_wpair[t * 2 + 1] = w1;
    }
}

// ================= stage 1: inner = silu(X@Wup) * (X@Wgate) =================
// BM=128, BN=64, BK=32. 8 warps = 4m x 2n, warp tile 32x32 (dual U/G acc).
// RAW distance 8 with only 8 live B-frags: terms ordered hh(U,G), lh(U,G), then hl(U,G).
#define S1_BOFF 18432u
#define S1_BUF  35328u
#define SMEM1   (3 * S1_BUF)

__global__ __launch_bounds__(256, 2) void stage1_mma() {
    const int e   = blockIdx.y >> 5;
    const int mt  = blockIdx.y & 31;
    const int cnt = g_count[e];
    const int m0  = mt * 128;
    if (m0 >= cnt) return;
    const int f0   = blockIdx.x * 64;
    const int tid  = threadIdx.x;
    const int lane = tid & 31;
    const int wid  = tid >> 5;
    const int wm   = wid & 3, wn = wid >> 2;

    __shared__ int rid_s[128];
    extern __shared__ char dsm[];
    const uint32_t sb = smem_u32(dsm);

    if (tid < 128) {
        int r = m0 + tid;
        rid_s[tid] = (r < cnt) ? g_plist[e * CAP + r] : 0;
    }
    __syncthreads();

    const int arow = tid >> 1, ahalf = tid & 1;
    const __nv_bfloat16* axh = g_xh + (size_t)(rid_s[arow] >> 1) * HH + ahalf * 16;
    const __nv_bfloat16* axl = g_xl + (size_t)(rid_s[arow] >> 1) * HH + ahalf * 16;
    const uint32_t adst = sb + arow * 144 + ahalf * 32;

    const int brow = tid >> 3, bseg = tid & 7;
    const __nv_bfloat16* wuh_p = g_wuh + (size_t)e * HH * FF;
    const __nv_bfloat16* wul_p = g_wul + (size_t)e * HH * FF;
    const __nv_bfloat16* wgh_p = g_wgh + (size_t)e * HH * FF;
    const __nv_bfloat16* wgl_p = g_wgl + (size_t)e * HH * FF;
    const uint32_t bdst = sb + S1_BOFF + brow * 528 + bseg * 16;
    const int bcol8 = f0 + bseg * 8;

#define S1_ISSUE(s, _bo) do {                                                  \
    int _k0 = (s) * 32;                                                        \
    uint32_t _ad = adst + (_bo);                                               \
    CP16(_ad,      axh + _k0); CP16(_ad + 16, axh + _k0 + 8);                  \
    CP16(_ad + 64, axl + _k0); CP16(_ad + 80, axl + _k0 + 8);                  \
    size_t _go = (size_t)(_k0 + brow) * FF + bcol8;                            \
    uint32_t _bd = bdst + (_bo);                                               \
    CP16(_bd,       wuh_p + _go);                                              \
    CP16(_bd + 128, wul_p + _go);                                              \
    CP16(_bd + 256, wgh_p + _go);                                              \
    CP16(_bd + 384, wgl_p + _go);                                              \
} while (0)

    uint32_t a_base[2];
#pragma unroll
    for (int i = 0; i < 2; i++)
        a_base[i] = sb + (wm * 32 + i * 16 + (lane & 15)) * 144 + (lane >> 4) * 16;
    const uint32_t b_base = sb + S1_BOFF + (lane & 15) * 528 + (wn * 32 + (lane >> 4) * 8) * 2;

    float aU[2][4][4], aG[2][4][4];
#pragma unroll
    for (int i = 0; i < 2; i++)
#pragma unroll
        for (int j = 0; j < 4; j++)
#pragma unroll
            for (int q = 0; q < 4; q++) { aU[i][j][q] = 0.f; aG[i][j][q] = 0.f; }

    S1_ISSUE(0, 0u); CPCOMMIT();
    S1_ISSUE(1, S1_BUF); CPCOMMIT();

    uint32_t bo = 0, ibo = 2 * S1_BUF;
    for (int s = 0; s < 32; s++) {
        CPWAIT1();
        __syncthreads();
        if (s + 2 < 32) S1_ISSUE(s + 2, ibo);
        CPCOMMIT();
#pragma unroll
        for (int kk = 0; kk < 32; kk += 16) {
            uint32_t ah[2][4], al[2][4];
#pragma unroll
            for (int i = 0; i < 2; i++) {
                uint32_t aa = a_base[i] + bo + kk * 2;
                LDSM4(ah[i], aa);
                LDSM4(al[i], aa + 64);
            }
#pragma unroll
            for (int jp = 0; jp < 2; jp++) {
                uint32_t ba = b_base + bo + kk * 528 + jp * 32;
                {
                    // hi B planes live (8 regs): terms hh and lh, U/G interleaved -> RAW dist 8
                    uint32_t bhU[4], bhG[4];
                    LDSM4T(bhU, ba);
                    LDSM4T(bhG, ba + 256);
#pragma unroll
                    for (int i = 0; i < 2; i++)
#pragma unroll
                        for (int j2 = 0; j2 < 2; j2++)
                            mma_bf16(aU[i][jp * 2 + j2], ah[i], bhU[2 * j2], bhU[2 * j2 + 1]);
#pragma unroll
                    for (int i = 0; i < 2; i++)
#pragma unroll
                        for (int j2 = 0; j2 < 2; j2++)
                            mma_bf16(aG[i][jp * 2 + j2], ah[i], bhG[2 * j2], bhG[2 * j2 + 1]);
#pragma unroll
                    for (int i = 0; i < 2; i++)
#pragma unroll
                        for (int j2 = 0; j2 < 2; j2++)
                            mma_bf16(aU[i][jp * 2 + j2], al[i], bhU[2 * j2], bhU[2 * j2 + 1]);
#pragma unroll
                    for (int i = 0; i < 2; i++)
#pragma unroll
                        for (int j2 = 0; j2 < 2; j2++)
                            mma_bf16(aG[i][jp * 2 + j2], al[i], bhG[2 * j2], bhG[2 * j2 + 1]);
                }
                {
                    // lo B planes replace hi (reg reuse): term hl, U/G interleaved
                    uint32_t blU[4], blG[4];
                    LDSM4T(blU, ba + 128);
                    LDSM4T(blG, ba + 384);
#pragma unroll
                    for (int i = 0; i < 2; i++)
#pragma unroll
                        for (int j2 = 0; j2 < 2; j2++)
                            mma_bf16(aU[i][jp * 2 + j2], ah[i], blU[2 * j2], blU[2 * j2 + 1]);
#pragma unroll
                    for (int i = 0; i < 2; i++)
#pragma unroll
                        for (int j2 = 0; j2 < 2; j2++)
                            mma_bf16(aG[i][jp * 2 + j2], ah[i], blG[2 * j2], blG[2 * j2 + 1]);
                }
            }
        }
        bo += S1_BUF;  if (bo == 3 * S1_BUF)  bo = 0;
        ibo += S1_BUF; if (ibo == 3 * S1_BUF) ibo = 0;
    }

    // epilogue: silu(U)*G -> inner hi/lo
    const int er = wm * 32 + (lane >> 2);
    const int ec = f0 + wn * 32 + 2 * (lane & 3);
#pragma unroll
    for (int i = 0; i < 2; i++)
#pragma unroll
        for (int half = 0; half < 2; half++) {
            int rr = er + i * 16 + half * 8;
            if (m0 + rr < cnt) {
                int id = rid_s[rr];
                size_t o = (size_t)id * FF + ec;
#pragma unroll
                for (int j = 0; j < 4; j++) {
                    float u0 = aU[i][j][half * 2 + 0], u1 = aU[i][j][half * 2 + 1];
                    float g0 = aG[i][j][half * 2 + 0], g1 = aG[i][j][half * 2 + 1];
                    float v0 = u0 / (1.f + __expf(-u0)) * g0;
                    float v1 = u1 / (1.f + __expf(-u1)) * g1;
                    uint32_t h0, l0, h1, l1;
                    splitf(v0, h0, l0); splitf(v1, h1, l1);
                    *(uint32_t*)(g_ih + o + j * 8) = h0 | (h1 << 16);
                    *(uint32_t*)(g_il + o + j * 8) = l0 | (l1 << 16);
                }
            }
        }
}

// ================= stage 2: g_part[kc][id] = w * (inner_kc @ Wdown_kc), split-K=2 =================
// BM=128, BN=128, BK=32, 32 k-steps per block. 8 warps = 4m x 2n, warp 32x64. NO atomics.
// RAW distance 8: jp processed in pairs, term-major across the pair.  (unchanged from R10)
#define S2_BOFF 18432u
#define S2_BUF  35328u
#define SMEM2   (3 * S2_BUF)
#define S2_KC   2
#define S2_KLEN (FF / S2_KC)   // 1024

__global__ __launch_bounds__(256, 2) void stage2_mma() {
    const int e   = blockIdx.y >> 5;
    const int mt  = blockIdx.y & 31;
    const int cnt = g_count[e];
    const int m0  = mt * 128;
    if (m0 >= cnt) return;
    const int kc   = blockIdx.x & (S2_KC - 1);
    const int h0   = (blockIdx.x >> 1) * 128;
    const int tid  = threadIdx.x;
    const int lane = tid & 31;
    const int wid  = tid >> 5;
    const int wm   = wid & 3, wn = wid >> 2;

    __shared__ int rid_s[128];
    extern __shared__ char dsm[];
    const uint32_t sb = smem_u32(dsm);

    if (tid < 128) {
        int r = m0 + tid;
        rid_s[tid] = (r < cnt) ? g_plist[e * CAP + r] : 0;
    }
    __syncthreads();

    const int arow = tid >> 1, ahalf = tid & 1;
    const __nv_bfloat16* axh = g_ih + (size_t)rid_s[arow] * FF + kc * S2_KLEN + ahalf * 16;
    const __nv_bfloat16* axl = g_il + (size_t)rid_s[arow] * FF + kc * S2_KLEN + ahalf * 16;
    const uint32_t adst = sb + arow * 144 + ahalf * 32;

    const __nv_bfloat16* wdh_p = g_wdh + (size_t)e * FF * HH + (size_t)kc * S2_KLEN * HH;
    const __nv_bfloat16* wdl_p = g_wdl + (size_t)e * FF * HH + (size_t)kc * S2_KLEN * HH;
    const int b0r = tid >> 4,          b0c = (tid & 15);
    const int b1r = (tid + 256) >> 4,  b1c = (tid & 15);
    const uint32_t bdst0 = sb + S2_BOFF + b0r * 528 + b0c * 16;
    const uint32_t bdst1 = sb + S2_BOFF + b1r * 528 + b1c * 16;
    const int bcol0 = h0 + b0c * 8, bcol1 = h0 + b1c * 8;

#define S2_ISSUE(s, _bo) do {                                                  \
    int _k0 = (s) * 32;                                                        \
    uint32_t _ad = adst + (_bo);                                               \
    CP16(_ad,      axh + _k0); CP16(_ad + 16, axh + _k0 + 8);                  \
    CP16(_ad + 64, axl + _k0); CP16(_ad + 80, axl + _k0 + 8);                  \
    size_t _g0 = (size_t)(_k0 + b0r) * HH + bcol0;                             \
    size_t _g1 = (size_t)(_k0 + b1r) * HH + bcol1;                             \
    CP16(bdst0 + (_bo),       wdh_p + _g0);                                    \
    CP16(bdst0 + (_bo) + 256, wdl_p + _g0);                                    \
    CP16(bdst1 + (_bo),       wdh_p + _g1);                                    \
    CP16(bdst1 + (_bo) + 256, wdl_p + _g1);                                    \
} while (0)

    uint32_t a_base[2];
#pragma unroll
    for (int i = 0; i < 2; i++)
        a_base[i] = sb + (wm * 32 + i * 16 + (lane & 15)) * 144 + (lane >> 4) * 16;
    const uint32_t b_base = sb + S2_BOFF + (lane & 15) * 528 + (wn * 64 + (lane >> 4) * 8) * 2;

    float acc[2][8][4];
#pragma unroll
    for (int i = 0; i < 2; i++)
#pragma unroll
        for (int j = 0; j < 8; j++)
#pragma unroll
            for (int q = 0; q < 4; q++) acc[i][j][q] = 0.f;

    S2_ISSUE(0, 0u); CPCOMMIT();
    S2_ISSUE(1, S2_BUF); CPCOMMIT();

    uint32_t bo = 0, ibo = 2 * S2_BUF;
    for (int s = 0; s < S2_KLEN / 32; s++) {
        CPWAIT1();
        __syncthreads();
        if (s + 2 < S2_KLEN / 32) S2_ISSUE(s + 2, ibo);
        CPCOMMIT();
#pragma unroll
        for (int kk = 0; kk < 32; kk += 16) {
            uint32_t ah[2][4], al[2][4];
#pragma unroll
            for (int i = 0; i < 2; i++) {
                uint32_t aa = a_base[i] + bo + kk * 2;
                LDSM4(ah[i], aa);
                LDSM4(al[i], aa + 64);
            }
#pragma unroll
            for (int jq = 0; jq < 2; jq++) {
                uint32_t ba0 = b_base + bo + kk * 528 + (jq * 2) * 32;
                uint32_t bh0[4], bl0[4], bh1[4], bl1[4];
                LDSM4T(bh0, ba0);
                LDSM4T(bl0, ba0 + 256);
                LDSM4T(bh1, ba0 + 32);
                LDSM4T(bl1, ba0 + 288);
                const int j0 = jq * 4, j1 = jq * 4 + 2;
#pragma unroll
                for (int i = 0; i < 2; i++)
#pragma unroll
                    for (int j2 = 0; j2 < 2; j2++)
                        mma_bf16(acc[i][j0 + j2], ah[i], bh0[2 * j2], bh0[2 * j2 + 1]);
#pragma unroll
                for (int i = 0; i < 2; i++)
#pragma unroll
                    for (int j2 = 0; j2 < 2; j2++)
                        mma_bf16(acc[i][j1 + j2], ah[i], bh1[2 * j2], bh1[2 * j2 + 1]);
#pragma unroll
                for (int i = 0; i < 2; i++)
#pragma unroll
                    for (int j2 = 0; j2 < 2; j2++)
                        mma_bf16(acc[i][j0 + j2], ah[i], bl0[2 * j2], bl0[2 * j2 + 1]);
#pragma unroll
                for (int i = 0; i < 2; i++)
#pragma unroll
                    for (int j2 = 0; j2 < 2; j2++)
                        mma_bf16(acc[i][j1 + j2], ah[i], bl1[2 * j2], bl1[2 * j2 + 1]);
#pragma unroll
                for (int i = 0; i < 2; i++)
#pragma unroll
                    for (int j2 = 0; j2 < 2; j2++)
                        mma_bf16(acc[i][j0 + j2], al[i], bh0[2 * j2], bh0[2 * j2 + 1]);
#pragma unroll
                for (int i = 0; i < 2; i++)
#pragma unroll
                    for (int j2 = 0; j2 < 2; j2++)
                        mma_bf16(acc[i][j1 + j2], al[i], bh1[2 * j2], bh1[2 * j2 + 1]);
            }
        }
        bo += S2_BUF;  if (bo == 3 * S2_BUF)  bo = 0;
        ibo += S2_BUF; if (ibo == 3 * S2_BUF) ibo = 0;
    }

    // epilogue: weighted partials -> g_part (plain vectorized stores, no atomics)
    const int er = wm * 32 + (lane >> 2);
#pragma unroll
    for (int i = 0; i < 2; i++)
#pragma unroll
        for (int half = 0; half < 2; half++) {
            int rr = er + i * 16 + half * 8;
            if (m0 + rr < cnt) {
                int   id = rid_s[rr];
                float w  = g_wpair[id];
                float* pp = g_part + ((size_t)kc * TT * 2 + id) * HH + h0 + wn * 64 + 2 * (lane & 3);
#pragma unroll
                for (int jp = 0; jp < 4; jp++)
#pragma unroll
                    for (int j2 = 0; j2 < 2; j2++) {
                        int c = jp * 16 + j2 * 8;
                        float2 v = make_float2(w * acc[i][jp * 2 + j2][half * 2 + 0],
                                               w * acc[i][jp * 2 + j2][half * 2 + 1]);
                        *(float2*)(pp + c) = v;
                    }
            }
        }
}

// ---------------- combine: out[t][h] = sum over {slot, kc} of g_part ----------------
__global__ __launch_bounds__(256) void combine_kernel(float4* __restrict__ out4) {
    int i = blockIdx.x * blockDim.x + threadIdx.x;    // < TT * HH / 4
    int t  = i >> 8;                                   // HH/4 = 256
    int h4 = i & 255;
    const float4* p = (const float4*)g_part;
    size_t r00 = ((size_t)0 * TT * 2 + 2 * t)     * (HH / 4) + h4;
    size_t r01 = ((size_t)0 * TT * 2 + 2 * t + 1) * (HH / 4) + h4;
    size_t r10 = ((size_t)1 * TT * 2 + 2 * t)     * (HH / 4) + h4;
    size_t r11 = ((size_t)1 * TT * 2 + 2 * t + 1) * (HH / 4) + h4;
    float4 a = p[r00], b = p[r01], c = p[r10], d = p[r11];
    out4[i] = make_float4((a.x + b.x) + (c.x + d.x),
                          (a.y + b.y) + (c.y + d.y),
                          (a.z + b.z) + (c.z + d.z),
                          (a.w + b.w) + (c.w + d.w));
}

// ---------------- launch ----------------
extern "C" void kernel_launch(void* const* d_in, const int* in_sizes, int n_in,
                              void* d_out, int out_size) {
    const float* x  = (const float*)d_in[0];
    const float* gw = (const float*)d_in[1];
    const float* wu = (const float*)d_in[2];
    const float* wg = (const float*)d_in[3];
    const float* wd = (const float*)d_in[4];
    float* out = (float*)d_out;

    cudaFuncSetAttribute(stage1_mma, cudaFuncAttributeMaxDynamicSharedMemorySize, SMEM1);
    cudaFuncSetAttribute(stage2_mma, cudaFuncAttributeMaxDynamicSharedMemorySize, SMEM2);

    split_all<<<(3 * NW4 + NX4 + 255) / 256, 256>>>((const float4*)wu, (const float4*)wg,
                                                    (const float4*)wd, (const float4*)x);
    router_kernel<<<TT, 128>>>(x, gw);
    stage1_mma<<<dim3(FF / 64, EE * 32), 256, SMEM1>>>();
    stage2_mma<<<dim3((HH / 128) * S2_KC, EE * 32), 256, SMEM2>>>();
    combine_kernel<<<TT * HH / 4 / 256, 256>>>((float4*)out);
}

// round 12
// speedup vs baseline: 1.0019x; 1.0019x over previous
#include <cuda_runtime.h>
#include <cuda_bf16.h>
#include <math.h>
#include <stdint.h>

#define TT 4096
#define HH 1024
#define EE 8
#define FF 2048
#define CAP 4096
#define NW (EE * HH * FF)
#define ND (EE * FF * HH)

// ---------------- scratch ----------------
__device__ int   g_count[EE];
__device__ int   g_plist[EE * CAP];
__device__ float g_wpair[TT * 2];
__device__ __align__(16) __nv_bfloat16 g_xh[TT * HH], g_xl[TT * HH];
__device__ __align__(16) __nv_bfloat16 g_wuh[NW], g_wul[NW];
__device__ __align__(16) __nv_bfloat16 g_wgh[NW], g_wgl[NW];
__device__ __align__(16) __nv_bfloat16 g_wdh[ND], g_wdl[ND];
__device__ __align__(16) __nv_bfloat16 g_ih[(size_t)TT * 2 * FF], g_il[(size_t)TT * 2 * FF];
// stage2 partials: [kc][packed id][HH]  (every slot written exactly once -> no zeroing)
__device__ __align__(16) float g_part[(size_t)2 * TT * 2 * HH];   // 67 MB

// ---------------- helpers ----------------
__device__ __forceinline__ uint32_t smem_u32(const void* p) {
    uint32_t a;
    asm("{ .reg .u64 t; cvta.to.shared.u64 t, %1; cvt.u32.u64 %0, t; }" : "=r"(a) : "l"(p));
    return a;
}
__device__ __forceinline__ void splitf(float f, uint32_t& h, uint32_t& l) {
    __nv_bfloat16 hb = __float2bfloat16_rn(f);
    float rf = f - __bfloat162float(hb);
    __nv_bfloat16 lb = __float2bfloat16_rn(rf);
    h = (uint32_t)__bfloat16_as_ushort(hb);
    l = (uint32_t)__bfloat16_as_ushort(lb);
}

#define CP16(dst, src)  asm volatile("cp.async.cg.shared.global [%0], [%1], 16;" :: "r"(dst), "l"(src))
#define CPCOMMIT()      asm volatile("cp.async.commit_group;" ::: "memory")
#define CPWAIT1()       asm volatile("cp.async.wait_group 1;" ::: "memory")

#define LDSM4(r, a)                                                                   \
    asm volatile("ldmatrix.sync.aligned.m8n8.x4.shared.b16 {%0,%1,%2,%3}, [%4];"      \
        : "=r"((r)[0]), "=r"((r)[1]), "=r"((r)[2]), "=r"((r)[3]) : "r"(a))
#define LDSM4T(r, a)                                                                  \
    asm volatile("ldmatrix.sync.aligned.m8n8.x4.trans.shared.b16 {%0,%1,%2,%3}, [%4];"\
        : "=r"((r)[0]), "=r"((r)[1]), "=r"((r)[2]), "=r"((r)[3]) : "r"(a))

__device__ __forceinline__ void mma_bf16(float* d, const uint32_t* a, uint32_t b0, uint32_t b1) {
    asm volatile(
        "mma.sync.aligned.m16n8k16.row.col.f32.bf16.bf16.f32 "
        "{%0,%1,%2,%3},{%4,%5,%6,%7},{%8,%9},{%0,%1,%2,%3};"
        : "+f"(d[0]), "+f"(d[1]), "+f"(d[2]), "+f"(d[3])
        : "r"(a[0]), "r"(a[1]), "r"(a[2]), "r"(a[3]), "r"(b0), "r"(b1));
}

// ---------------- fused split prepass (also resets expert counters) ----------------
#define NW4 (NW / 4)
#define NX4 (TT * HH / 4)
__global__ __launch_bounds__(256) void split_all(const float4* __restrict__ wu,
                                                 const float4* __restrict__ wg,
                                                 const float4* __restrict__ wd,
                                                 const float4* __restrict__ x) {
    if (blockIdx.x == 0 && threadIdx.x < EE) g_count[threadIdx.x] = 0;
    int i = blockIdx.x * blockDim.x + threadIdx.x;
    const float4* src;
    __nv_bfloat16 *hp, *lp;
    int j;
    if (i < NW4)               { src = wu; hp = g_wuh; lp = g_wul; j = i; }
    else if (i < 2 * NW4)      { src = wg; hp = g_wgh; lp = g_wgl; j = i - NW4; }
    else if (i < 3 * NW4)      { src = wd; hp = g_wdh; lp = g_wdl; j = i - 2 * NW4; }
    else if (i < 3 * NW4 + NX4){ src = x;  hp = g_xh;  lp = g_xl;  j = i - 3 * NW4; }
    else return;
    float4 v = src[j];
    uint32_t h0, h1, h2, h3, l0, l1, l2, l3;
    splitf(v.x, h0, l0); splitf(v.y, h1, l1);
    splitf(v.z, h2, l2); splitf(v.w, h3, l3);
    ((uint2*)hp)[j] = make_uint2(h0 | (h1 << 16), h2 | (h3 << 16));
    ((uint2*)lp)[j] = make_uint2(l0 | (l1 << 16), l2 | (l3 << 16));
}

// ---------------- router ----------------
__global__ __launch_bounds__(128) void router_kernel(const float* __restrict__ x,
                                                     const float* __restrict__ gw) {
    int t = blockIdx.x, tid = threadIdx.x;
    const float* xp = x + (size_t)t * HH;
    double part[EE];
#pragma unroll
    for (int e = 0; e < EE; e++) part[e] = 0.0;
#pragma unroll
    for (int s = 0; s < HH / 128; s++) {
        int h = tid + s * 128;
        double xv = (double)xp[h];
#pragma unroll
        for (int e = 0; e < EE; e++) part[e] += xv * (double)gw[h * EE + e];
    }
    __shared__ double red[EE][128];
#pragma unroll
    for (int e = 0; e < EE; e++) red[e][tid] = part[e];
    __syncthreads();
    for (int st = 64; st > 0; st >>= 1) {
        if (tid < st) {
#pragma unroll
            for (int e = 0; e < EE; e++) red[e][tid] += red[e][tid + st];
        }
        __syncthreads();
    }
    if (tid == 0) {
        double l[EE];
#pragma unroll
        for (int e = 0; e < EE; e++) l[e] = red[e][0];
        int i0 = 0;
        for (int e = 1; e < EE; e++) if (l[e] > l[i0]) i0 = e;
        int i1 = (i0 == 0) ? 1 : 0;
        for (int e = 0; e < EE; e++) if (e != i0 && l[e] > l[i1]) i1 = e;
        double d  = exp(l[i1] - l[i0]);
        float  w0 = (float)(1.0 / (1.0 + d));
        float  w1 = (float)(d / (1.0 + d));
        int p0 = atomicAdd(&g_count[i0], 1);
        g_plist[i0 * CAP + p0] = t * 2;
        int p1 = atomicAdd(&g_count[i1], 1);
        g_plist[i1 * CAP + p1] = t * 2 + 1;
        g_wpair[t * 2]     = w0;
        g_wpair[t * 2 + 1] = w1;
    }
}

// ================= stage 1: inner = silu(X@Wup) * (X@Wgate)  (R8 schedule, 571.6us measured) =================
// BM=128, BN=64, BK=32. 8 warps = 4m x 2n, warp tile 32x32 (dual U/G acc).
// Term-major per plane: U(hh,hl,lh) then G(hh,hl,lh).
#define S1_BOFF 18432u
#define S1_BUF  35328u
#define SMEM1   (3 * S1_BUF)

__global__ __launch_bounds__(256, 2) void stage1_mma() {
    const int e   = blockIdx.y >> 5;
    const int mt  = blockIdx.y & 31;
    const int cnt = g_count[e];
    const int m0  = mt * 128;
    if (m0 >= cnt) return;
    const int f0   = blockIdx.x * 64;
    const int tid  = threadIdx.x;
    const int lane = tid & 31;
    const int wid  = tid >> 5;
    const int wm   = wid & 3, wn = wid >> 2;

    __shared__ int rid_s[128];
    extern __shared__ char dsm[];
    const uint32_t sb = smem_u32(dsm);

    if (tid < 128) {
        int r = m0 + tid;
        rid_s[tid] = (r < cnt) ? g_plist[e * CAP + r] : 0;
    }
    __syncthreads();

    const int arow = tid >> 1, ahalf = tid & 1;
    const __nv_bfloat16* axh = g_xh + (size_t)(rid_s[arow] >> 1) * HH + ahalf * 16;
    const __nv_bfloat16* axl = g_xl + (size_t)(rid_s[arow] >> 1) * HH + ahalf * 16;
    const uint32_t adst = sb + arow * 144 + ahalf * 32;

    const int brow = tid >> 3, bseg = tid & 7;
    const __nv_bfloat16* wuh_p = g_wuh + (size_t)e * HH * FF;
    const __nv_bfloat16* wul_p = g_wul + (size_t)e * HH * FF;
    const __nv_bfloat16* wgh_p = g_wgh + (size_t)e * HH * FF;
    const __nv_bfloat16* wgl_p = g_wgl + (size_t)e * HH * FF;
    const uint32_t bdst = sb + S1_BOFF + brow * 528 + bseg * 16;
    const int bcol8 = f0 + bseg * 8;

#define S1_ISSUE(s, _bo) do {                                                  \
    int _k0 = (s) * 32;                                                        \
    uint32_t _ad = adst + (_bo);                                               \
    CP16(_ad,      axh + _k0); CP16(_ad + 16, axh + _k0 + 8);                  \
    CP16(_ad + 64, axl + _k0); CP16(_ad + 80, axl + _k0 + 8);                  \
    size_t _go = (size_t)(_k0 + brow) * FF + bcol8;                            \
    uint32_t _bd = bdst + (_bo);                                               \
    CP16(_bd,       wuh_p + _go);                                              \
    CP16(_bd + 128, wul_p + _go);                                              \
    CP16(_bd + 256, wgh_p + _go);                                              \
    CP16(_bd + 384, wgl_p + _go);                                              \
} while (0)

    uint32_t a_base[2];
#pragma unroll
    for (int i = 0; i < 2; i++)
        a_base[i] = sb + (wm * 32 + i * 16 + (lane & 15)) * 144 + (lane >> 4) * 16;
    const uint32_t b_base = sb + S1_BOFF + (lane & 15) * 528 + (wn * 32 + (lane >> 4) * 8) * 2;

    float aU[2][4][4], aG[2][4][4];
#pragma unroll
    for (int i = 0; i < 2; i++)
#pragma unroll
        for (int j = 0; j < 4; j++)
#pragma unroll
            for (int q = 0; q < 4; q++) { aU[i][j][q] = 0.f; aG[i][j][q] = 0.f; }

    S1_ISSUE(0, 0u); CPCOMMIT();
    S1_ISSUE(1, S1_BUF); CPCOMMIT();

    uint32_t bo = 0, ibo = 2 * S1_BUF;
    for (int s = 0; s < 32; s++) {
        CPWAIT1();
        __syncthreads();
        if (s + 2 < 32) S1_ISSUE(s + 2, ibo);
        CPCOMMIT();
#pragma unroll
        for (int kk = 0; kk < 32; kk += 16) {
            uint32_t ah[2][4], al[2][4];
#pragma unroll
            for (int i = 0; i < 2; i++) {
                uint32_t aa = a_base[i] + bo + kk * 2;
                LDSM4(ah[i], aa);
                LDSM4(al[i], aa + 64);
            }
#pragma unroll
            for (int jp = 0; jp < 2; jp++) {
                uint32_t ba = b_base + bo + kk * 528 + jp * 32;
                uint32_t bh[4], bl[4];
                LDSM4T(bh, ba);
                LDSM4T(bl, ba + 128);
#pragma unroll
                for (int i = 0; i < 2; i++)
#pragma unroll
                    for (int j2 = 0; j2 < 2; j2++)
                        mma_bf16(aU[i][jp * 2 + j2], ah[i], bh[2 * j2], bh[2 * j2 + 1]);
#pragma unroll
                for (int i = 0; i < 2; i++)
#pragma unroll
                    for (int j2 = 0; j2 < 2; j2++)
                        mma_bf16(aU[i][jp * 2 + j2], ah[i], bl[2 * j2], bl[2 * j2 + 1]);
#pragma unroll
                for (int i = 0; i < 2; i++)
#pragma unroll
                    for (int j2 = 0; j2 < 2; j2++)
                        mma_bf16(aU[i][jp * 2 + j2], al[i], bh[2 * j2], bh[2 * j2 + 1]);
                LDSM4T(bh, ba + 256);
                LDSM4T(bl, ba + 384);
#pragma unroll
                for (int i = 0; i < 2; i++)
#pragma unroll
                    for (int j2 = 0; j2 < 2; j2++)
                        mma_bf16(aG[i][jp * 2 + j2], ah[i], bh[2 * j2], bh[2 * j2 + 1]);
#pragma unroll
                for (int i = 0; i < 2; i++)
#pragma unroll
                    for (int j2 = 0; j2 < 2; j2++)
                        mma_bf16(aG[i][jp * 2 + j2], ah[i], bl[2 * j2], bl[2 * j2 + 1]);
#pragma unroll
                for (int i = 0; i < 2; i++)
#pragma unroll
                    for (int j2 = 0; j2 < 2; j2++)
                        mma_bf16(aG[i][jp * 2 + j2], al[i], bh[2 * j2], bh[2 * j2 + 1]);
            }
        }
        bo += S1_BUF;  if (bo == 3 * S1_BUF)  bo = 0;
        ibo += S1_BUF; if (ibo == 3 * S1_BUF) ibo = 0;
    }

    // epilogue: silu(U)*G -> inner hi/lo
    const int er = wm * 32 + (lane >> 2);
    const int ec = f0 + wn * 32 + 2 * (lane & 3);
#pragma unroll
    for (int i = 0; i < 2; i++)
#pragma unroll
        for (int half = 0; half < 2; half++) {
            int rr = er + i * 16 + half * 8;
            if (m0 + rr < cnt) {
                int id = rid_s[rr];
                size_t o = (size_t)id * FF + ec;
#pragma unroll
                for (int j = 0; j < 4; j++) {
                    float u0 = aU[i][j][half * 2 + 0], u1 = aU[i][j][half * 2 + 1];
                    float g0 = aG[i][j][half * 2 + 0], g1 = aG[i][j][half * 2 + 1];
                    float v0 = u0 / (1.f + __expf(-u0)) * g0;
                    float v1 = u1 / (1.f + __expf(-u1)) * g1;
                    uint32_t h0, l0, h1, l1;
                    splitf(v0, h0, l0); splitf(v1, h1, l1);
                    *(uint32_t*)(g_ih + o + j * 8) = h0 | (h1 << 16);
                    *(uint32_t*)(g_il + o + j * 8) = l0 | (l1 << 16);
                }
            }
        }
}

// ================= stage 2 (R10 schedule, 292.4us measured): split-K=2, no atomics =================
// BM=128, BN=128, BK=32, 32 k-steps per block. 8 warps = 4m x 2n, warp 32x64.
// RAW distance 8: jp processed in pairs, term-major across the pair.
#define S2_BOFF 18432u
#define S2_BUF  35328u
#define SMEM2   (3 * S2_BUF)
#define S2_KC   2
#define S2_KLEN (FF / S2_KC)   // 1024

__global__ __launch_bounds__(256, 2) void stage2_mma() {
    const int e   = blockIdx.y >> 5;
    const int mt  = blockIdx.y & 31;
    const int cnt = g_count[e];
    const int m0  = mt * 128;
    if (m0 >= cnt) return;
    const int kc   = blockIdx.x & (S2_KC - 1);
    const int h0   = (blockIdx.x >> 1) * 128;
    const int tid  = threadIdx.x;
    const int lane = tid & 31;
    const int wid  = tid >> 5;
    const int wm   = wid & 3, wn = wid >> 2;

    __shared__ int rid_s[128];
    extern __shared__ char dsm[];
    const uint32_t sb = smem_u32(dsm);

    if (tid < 128) {
        int r = m0 + tid;
        rid_s[tid] = (r < cnt) ? g_plist[e * CAP + r] : 0;
    }
    __syncthreads();

    const int arow = tid >> 1, ahalf = tid & 1;
    const __nv_bfloat16* axh = g_ih + (size_t)rid_s[arow] * FF + kc * S2_KLEN + ahalf * 16;
    const __nv_bfloat16* axl = g_il + (size_t)rid_s[arow] * FF + kc * S2_KLEN + ahalf * 16;
    const uint32_t adst = sb + arow * 144 + ahalf * 32;

    const __nv_bfloat16* wdh_p = g_wdh + (size_t)e * FF * HH + (size_t)kc * S2_KLEN * HH;
    const __nv_bfloat16* wdl_p = g_wdl + (size_t)e * FF * HH + (size_t)kc * S2_KLEN * HH;
    const int b0r = tid >> 4,          b0c = (tid & 15);
    const int b1r = (tid + 256) >> 4,  b1c = (tid & 15);
    const uint32_t bdst0 = sb + S2_BOFF + b0r * 528 + b0c * 16;
    const uint32_t bdst1 = sb + S2_BOFF + b1r * 528 + b1c * 16;
    const int bcol0 = h0 + b0c * 8, bcol1 = h0 + b1c * 8;

#define S2_ISSUE(s, _bo) do {                                                  \
    int _k0 = (s) * 32;                                                        \
    uint32_t _ad = adst + (_bo);                                               \
    CP16(_ad,      axh + _k0); CP16(_ad + 16, axh + _k0 + 8);                  \
    CP16(_ad + 64, axl + _k0); CP16(_ad + 80, axl + _k0 + 8);                  \
    size_t _g0 = (size_t)(_k0 + b0r) * HH + bcol0;                             \
    size_t _g1 = (size_t)(_k0 + b1r) * HH + bcol1;                             \
    CP16(bdst0 + (_bo),       wdh_p + _g0);                                    \
    CP16(bdst0 + (_bo) + 256, wdl_p + _g0);                                    \
    CP16(bdst1 + (_bo),       wdh_p + _g1);                                    \
    CP16(bdst1 + (_bo) + 256, wdl_p + _g1);                                    \
} while (0)

    uint32_t a_base[2];
#pragma unroll
    for (int i = 0; i < 2; i++)
        a_base[i] = sb + (wm * 32 + i * 16 + (lane & 15)) * 144 + (lane >> 4) * 16;
    const uint32_t b_base = sb + S2_BOFF + (lane & 15) * 528 + (wn * 64 + (lane >> 4) * 8) * 2;

    float acc[2][8][4];
#pragma unroll
    for (int i = 0; i < 2; i++)
#pragma unroll
        for (int j = 0; j < 8; j++)
#pragma unroll
            for (int q = 0; q < 4; q++) acc[i][j][q] = 0.f;

    S2_ISSUE(0, 0u); CPCOMMIT();
    S2_ISSUE(1, S2_BUF); CPCOMMIT();

    uint32_t bo = 0, ibo = 2 * S2_BUF;
    for (int s = 0; s < S2_KLEN / 32; s++) {
        CPWAIT1();
        __syncthreads();
        if (s + 2 < S2_KLEN / 32) S2_ISSUE(s + 2, ibo);
        CPCOMMIT();
#pragma unroll
        for (int kk = 0; kk < 32; kk += 16) {
            uint32_t ah[2][4], al[2][4];
#pragma unroll
            for (int i = 0; i < 2; i++) {
                uint32_t aa = a_base[i] + bo + kk * 2;
                LDSM4(ah[i], aa);
                LDSM4(al[i], aa + 64);
            }
#pragma unroll
            for (int jq = 0; jq < 2; jq++) {
                uint32_t ba0 = b_base + bo + kk * 528 + (jq * 2) * 32;
                uint32_t bh0[4], bl0[4], bh1[4], bl1[4];
                LDSM4T(bh0, ba0);
                LDSM4T(bl0, ba0 + 256);
                LDSM4T(bh1, ba0 + 32);
                LDSM4T(bl1, ba0 + 288);
                const int j0 = jq * 4, j1 = jq * 4 + 2;
#pragma unroll
                for (int i = 0; i < 2; i++)
#pragma unroll
                    for (int j2 = 0; j2 < 2; j2++)
                        mma_bf16(acc[i][j0 + j2], ah[i], bh0[2 * j2], bh0[2 * j2 + 1]);
#pragma unroll
                for (int i = 0; i < 2; i++)
#pragma unroll
                    for (int j2 = 0; j2 < 2; j2++)
                        mma_bf16(acc[i][j1 + j2], ah[i], bh1[2 * j2], bh1[2 * j2 + 1]);
#pragma unroll
                for (int i = 0; i < 2; i++)
#pragma unroll
                    for (int j2 = 0; j2 < 2; j2++)
                        mma_bf16(acc[i][j0 + j2], ah[i], bl0[2 * j2], bl0[2 * j2 + 1]);
#pragma unroll
                for (int i = 0; i < 2; i++)
#pragma unroll
                    for (int j2 = 0; j2 < 2; j2++)
                        mma_bf16(acc[i][j1 + j2], ah[i], bl1[2 * j2], bl1[2 * j2 + 1]);
#pragma unroll
                for (int i = 0; i < 2; i++)
#pragma unroll
                    for (int j2 = 0; j2 < 2; j2++)
                        mma_bf16(acc[i][j0 + j2], al[i], bh0[2 * j2], bh0[2 * j2 + 1]);
#pragma unroll
                for (int i = 0; i < 2; i++)
#pragma unroll
                    for (int j2 = 0; j2 < 2; j2++)
                        mma_bf16(acc[i][j1 + j2], al[i], bh1[2 * j2], bh1[2 * j2 + 1]);
            }
        }
        bo += S2_BUF;  if (bo == 3 * S2_BUF)  bo = 0;
        ibo += S2_BUF; if (ibo == 3 * S2_BUF) ibo = 0;
    }

    // epilogue: weighted partials -> g_part (plain vectorized stores, no atomics)
    const int er = wm * 32 + (lane >> 2);
#pragma unroll
    for (int i = 0; i < 2; i++)
#pragma unroll
        for (int half = 0; half < 2; half++) {
            int rr = er + i * 16 + half * 8;
            if (m0 + rr < cnt) {
                int   id = rid_s[rr];
                float w  = g_wpair[id];
                float* pp = g_part + ((size_t)kc * TT * 2 + id) * HH + h0 + wn * 64 + 2 * (lane & 3);
#pragma unroll
                for (int jp = 0; jp < 4; jp++)
#pragma unroll
                    for (int j2 = 0; j2 < 2; j2++) {
                        int c = jp * 16 + j2 * 8;
                        float2 v = make_float2(w * acc[i][jp * 2 + j2][half * 2 + 0],
                                               w * acc[i][jp * 2 + j2][half * 2 + 1]);
                        *(float2*)(pp + c) = v;
                    }
            }
        }
}

// ---------------- combine: out[t][h] = sum over {slot, kc} of g_part ----------------
__global__ __launch_bounds__(256) void combine_kernel(float4* __restrict__ out4) {
    int i = blockIdx.x * blockDim.x + threadIdx.x;    // < TT * HH / 4
    int t  = i >> 8;                                   // HH/4 = 256
    int h4 = i & 255;
    const float4* p = (const float4*)g_part;
    size_t r00 = ((size_t)0 * TT * 2 + 2 * t)     * (HH / 4) + h4;
    size_t r01 = ((size_t)0 * TT * 2 + 2 * t + 1) * (HH / 4) + h4;
    size_t r10 = ((size_t)1 * TT * 2 + 2 * t)     * (HH / 4) + h4;
    size_t r11 = ((size_t)1 * TT * 2 + 2 * t + 1) * (HH / 4) + h4;
    float4 a = p[r00], b = p[r01], c = p[r10], d = p[r11];
    out4[i] = make_float4((a.x + b.x) + (c.x + d.x),
                          (a.y + b.y) + (c.y + d.y),
                          (a.z + b.z) + (c.z + d.z),
                          (a.w + b.w) + (c.w + d.w));
}

// ---------------- launch ----------------
extern "C" void kernel_launch(void* const* d_in, const int* in_sizes, int n_in,
                              void* d_out, int out_size) {
    const float* x  = (const float*)d_in[0];
    const float* gw = (const float*)d_in[1];
    const float* wu = (const float*)d_in[2];
    const float* wg = (const float*)d_in[3];
    const float* wd = (const float*)d_in[4];
    float* out = (float*)d_out;

    cudaFuncSetAttribute(stage1_mma, cudaFuncAttributeMaxDynamicSharedMemorySize, SMEM1);
    cudaFuncSetAttribute(stage2_mma, cudaFuncAttributeMaxDynamicSharedMemorySize, SMEM2);

    split_all<<<(3 * NW4 + NX4 + 255) / 256, 256>>>((const float4*)wu, (const float4*)wg,
                                                    (const float4*)wd, (const float4*)x);
    router_kernel<<<TT, 128>>>(x, gw);
    stage1_mma<<<dim3(FF / 64, EE * 32), 256, SMEM1>>>();
    stage2_mma<<<dim3((HH / 128) * S2_KC, EE * 32), 256, SMEM2>>>();
    combine_kernel<<<TT * HH / 4 / 256, 256>>>((float4*)out);
}

// round 13
// speedup vs baseline: 1.1020x; 1.1000x over previous
#include <cuda_runtime.h>
#include <cuda_bf16.h>
#include <math.h>
#include <stdint.h>

#define TT 4096
#define HH 1024
#define EE 8
#define FF 2048
#define CAP 4096
#define NW (EE * HH * FF)
#define ND (EE * FF * HH)

// ---------------- scratch ----------------
__device__ int   g_count[EE];          // zero at load; re-zeroed by combine_kernel each run
__device__ int   g_plist[EE * CAP];
__device__ float g_wpair[TT * 2];
__device__ __align__(16) __nv_bfloat16 g_xh[TT * HH], g_xl[TT * HH];
__device__ __align__(16) __nv_bfloat16 g_wuh[NW], g_wul[NW];
__device__ __align__(16) __nv_bfloat16 g_wgh[NW], g_wgl[NW];
__device__ __align__(16) __nv_bfloat16 g_wdh[ND], g_wdl[ND];
__device__ __align__(16) __nv_bfloat16 g_ih[(size_t)TT * 2 * FF], g_il[(size_t)TT * 2 * FF];
__device__ __align__(16) float g_part[(size_t)2 * TT * 2 * HH];   // 67 MB

// ---------------- helpers ----------------
__device__ __forceinline__ uint32_t smem_u32(const void* p) {
    uint32_t a;
    asm("{ .reg .u64 t; cvta.to.shared.u64 t, %1; cvt.u32.u64 %0, t; }" : "=r"(a) : "l"(p));
    return a;
}
__device__ __forceinline__ void splitf(float f, uint32_t& h, uint32_t& l) {
    __nv_bfloat16 hb = __float2bfloat16_rn(f);
    float rf = f - __bfloat162float(hb);
    __nv_bfloat16 lb = __float2bfloat16_rn(rf);
    h = (uint32_t)__bfloat16_as_ushort(hb);
    l = (uint32_t)__bfloat16_as_ushort(lb);
}

#define CP16(dst, src)  asm volatile("cp.async.cg.shared.global [%0], [%1], 16;" :: "r"(dst), "l"(src))
#define CPCOMMIT()      asm volatile("cp.async.commit_group;" ::: "memory")
#define CPWAIT1()       asm volatile("cp.async.wait_group 1;" ::: "memory")

#define LDSM4(r, a)                                                                   \
    asm volatile("ldmatrix.sync.aligned.m8n8.x4.shared.b16 {%0,%1,%2,%3}, [%4];"      \
        : "=r"((r)[0]), "=r"((r)[1]), "=r"((r)[2]), "=r"((r)[3]) : "r"(a))
#define LDSM4T(r, a)                                                                  \
    asm volatile("ldmatrix.sync.aligned.m8n8.x4.trans.shared.b16 {%0,%1,%2,%3}, [%4];"\
        : "=r"((r)[0]), "=r"((r)[1]), "=r"((r)[2]), "=r"((r)[3]) : "r"(a))

__device__ __forceinline__ void mma_bf16(float* d, const uint32_t* a, uint32_t b0, uint32_t b1) {
    asm volatile(
        "mma.sync.aligned.m16n8k16.row.col.f32.bf16.bf16.f32 "
        "{%0,%1,%2,%3},{%4,%5,%6,%7},{%8,%9},{%0,%1,%2,%3};"
        : "+f"(d[0]), "+f"(d[1]), "+f"(d[2]), "+f"(d[3])
        : "r"(a[0]), "r"(a[1]), "r"(a[2]), "r"(a[3]), "r"(b0), "r"(b1));
}

// ---------------- fused prep: router (first RB blocks) + split (rest) ----------------
#define NW4 (NW / 4)
#define NX4 (TT * HH / 4)
#define RB  (TT / 8)                       // 512 router blocks, 8 tokens (warps) each
#define SPLIT_BLOCKS ((3 * NW4 + NX4) / 256)

__global__ __launch_bounds__(256) void prep_kernel(const float4* __restrict__ wu,
                                                   const float4* __restrict__ wg,
                                                   const float4* __restrict__ wd,
                                                   const float4* __restrict__ x4,
                                                   const float*  __restrict__ xf,
                                                   const float*  __restrict__ gwf) {
    if (blockIdx.x < RB) {
        // ---- router: warp per token; fp32 products, fp64 group accumulation ----
        const int warp = threadIdx.x >> 5, lane = threadIdx.x & 31;
        const int t = blockIdx.x * 8 + warp;
        const float* xp = xf + (size_t)t * HH;

        double acc[EE];
#pragma unroll
        for (int e = 0; e < EE; e++) acc[e] = 0.0;

#pragma unroll
        for (int g = 0; g < 4; g++) {
            float p[EE];
#pragma unroll
            for (int e = 0; e < EE; e++) p[e] = 0.f;
#pragma unroll
            for (int j8 = 0; j8 < 8; j8++) {
                int h = lane + 32 * (g * 8 + j8);
                float xv = xp[h];
                float4 w0 = *(const float4*)(gwf + h * EE);
                float4 w1 = *(const float4*)(gwf + h * EE + 4);
                p[0] += xv * w0.x; p[1] += xv * w0.y;
                p[2] += xv * w0.z; p[3] += xv * w0.w;
                p[4] += xv * w1.x; p[5] += xv * w1.y;
                p[6] += xv * w1.z; p[7] += xv * w1.w;
            }
#pragma unroll
            for (int e = 0; e < EE; e++) acc[e] += (double)p[e];
        }
#pragma unroll
        for (int off = 16; off > 0; off >>= 1)
#pragma unroll
            for (int e = 0; e < EE; e++)
                acc[e] += __shfl_down_sync(0xffffffffu, acc[e], off);

        if (lane == 0) {
            int i0 = 0;
            for (int e = 1; e < EE; e++) if (acc[e] > acc[i0]) i0 = e;
            int i1 = (i0 == 0) ? 1 : 0;
            for (int e = 0; e < EE; e++) if (e != i0 && acc[e] > acc[i1]) i1 = e;
            double d  = exp(acc[i1] - acc[i0]);
            float  w0 = (float)(1.0 / (1.0 + d));
            float  w1 = (float)(d / (1.0 + d));
            int p0 = atomicAdd(&g_count[i0], 1);
            g_plist[i0 * CAP + p0] = t * 2;
            int p1 = atomicAdd(&g_count[i1], 1);
            g_plist[i1 * CAP + p1] = t * 2 + 1;
            g_wpair[t * 2]     = w0;
            g_wpair[t * 2 + 1] = w1;
        }
        return;
    }

    // ---- split: fp32 -> bf16 hi/lo planes ----
    int i = (blockIdx.x - RB) * blockDim.x + threadIdx.x;
    const float4* src;
    __nv_bfloat16 *hp, *lp;
    int j;
    if (i < NW4)               { src = wu; hp = g_wuh; lp = g_wul; j = i; }
    else if (i < 2 * NW4)      { src = wg; hp = g_wgh; lp = g_wgl; j = i - NW4; }
    else if (i < 3 * NW4)      { src = wd; hp = g_wdh; lp = g_wdl; j = i - 2 * NW4; }
    else if (i < 3 * NW4 + NX4){ src = x4; hp = g_xh;  lp = g_xl;  j = i - 3 * NW4; }
    else return;
    float4 v = src[j];
    uint32_t h0, h1, h2, h3, l0, l1, l2, l3;
    splitf(v.x, h0, l0); splitf(v.y, h1, l1);
    splitf(v.z, h2, l2); splitf(v.w, h3, l3);
    ((uint2*)hp)[j] = make_uint2(h0 | (h1 << 16), h2 | (h3 << 16));
    ((uint2*)lp)[j] = make_uint2(l0 | (l1 << 16), l2 | (l3 << 16));
}

// ================= stage 1: inner = silu(X@Wup) * (X@Wgate)  (R8 schedule) =================
#define S1_BOFF 18432u
#define S1_BUF  35328u
#define SMEM1   (3 * S1_BUF)

__global__ __launch_bounds__(256, 2) void stage1_mma() {
    const int e   = blockIdx.y >> 5;
    const int mt  = blockIdx.y & 31;
    const int cnt = g_count[e];
    const int m0  = mt * 128;
    if (m0 >= cnt) return;
    const int f0   = blockIdx.x * 64;
    const int tid  = threadIdx.x;
    const int lane = tid & 31;
    const int wid  = tid >> 5;
    const int wm   = wid & 3, wn = wid >> 2;

    __shared__ int rid_s[128];
    extern __shared__ char dsm[];
    const uint32_t sb = smem_u32(dsm);

    if (tid < 128) {
        int r = m0 + tid;
        rid_s[tid] = (r < cnt) ? g_plist[e * CAP + r] : 0;
    }
    __syncthreads();

    const int arow = tid >> 1, ahalf = tid & 1;
    const __nv_bfloat16* axh = g_xh + (size_t)(rid_s[arow] >> 1) * HH + ahalf * 16;
    const __nv_bfloat16* axl = g_xl + (size_t)(rid_s[arow] >> 1) * HH + ahalf * 16;
    const uint32_t adst = sb + arow * 144 + ahalf * 32;

    const int brow = tid >> 3, bseg = tid & 7;
    const __nv_bfloat16* wuh_p = g_wuh + (size_t)e * HH * FF;
    const __nv_bfloat16* wul_p = g_wul + (size_t)e * HH * FF;
    const __nv_bfloat16* wgh_p = g_wgh + (size_t)e * HH * FF;
    const __nv_bfloat16* wgl_p = g_wgl + (size_t)e * HH * FF;
    const uint32_t bdst = sb + S1_BOFF + brow * 528 + bseg * 16;
    const int bcol8 = f0 + bseg * 8;

#define S1_ISSUE(s, _bo) do {                                                  \
    int _k0 = (s) * 32;                                                        \
    uint32_t _ad = adst + (_bo);                                               \
    CP16(_ad,      axh + _k0); CP16(_ad + 16, axh + _k0 + 8);                  \
    CP16(_ad + 64, axl + _k0); CP16(_ad + 80, axl + _k0 + 8);                  \
    size_t _go = (size_t)(_k0 + brow) * FF + bcol8;                            \
    uint32_t _bd = bdst + (_bo);                                               \
    CP16(_bd,       wuh_p + _go);                                              \
    CP16(_bd + 128, wul_p + _go);                                              \
    CP16(_bd + 256, wgh_p + _go);                                              \
    CP16(_bd + 384, wgl_p + _go);                                              \
} while (0)

    uint32_t a_base[2];
#pragma unroll
    for (int i = 0; i < 2; i++)
        a_base[i] = sb + (wm * 32 + i * 16 + (lane & 15)) * 144 + (lane >> 4) * 16;
    const uint32_t b_base = sb + S1_BOFF + (lane & 15) * 528 + (wn * 32 + (lane >> 4) * 8) * 2;

    float aU[2][4][4], aG[2][4][4];
#pragma unroll
    for (int i = 0; i < 2; i++)
#pragma unroll
        for (int j = 0; j < 4; j++)
#pragma unroll
            for (int q = 0; q < 4; q++) { aU[i][j][q] = 0.f; aG[i][j][q] = 0.f; }

    S1_ISSUE(0, 0u); CPCOMMIT();
    S1_ISSUE(1, S1_BUF); CPCOMMIT();

    uint32_t bo = 0, ibo = 2 * S1_BUF;
    for (int s = 0; s < 32; s++) {
        CPWAIT1();
        __syncthreads();
        if (s + 2 < 32) S1_ISSUE(s + 2, ibo);
        CPCOMMIT();
#pragma unroll
        for (int kk = 0; kk < 32; kk += 16) {
            uint32_t ah[2][4], al[2][4];
#pragma unroll
            for (int i = 0; i < 2; i++) {
                uint32_t aa = a_base[i] + bo + kk * 2;
                LDSM4(ah[i], aa);
                LDSM4(al[i], aa + 64);
            }
#pragma unroll
            for (int jp = 0; jp < 2; jp++) {
                uint32_t ba = b_base + bo + kk * 528 + jp * 32;
                uint32_t bh[4], bl[4];
                LDSM4T(bh, ba);
                LDSM4T(bl, ba + 128);
#pragma unroll
                for (int i = 0; i < 2; i++)
#pragma unroll
                    for (int j2 = 0; j2 < 2; j2++)
                        mma_bf16(aU[i][jp * 2 + j2], ah[i], bh[2 * j2], bh[2 * j2 + 1]);
#pragma unroll
                for (int i = 0; i < 2; i++)
#pragma unroll
                    for (int j2 = 0; j2 < 2; j2++)
                        mma_bf16(aU[i][jp * 2 + j2], ah[i], bl[2 * j2], bl[2 * j2 + 1]);
#pragma unroll
                for (int i = 0; i < 2; i++)
#pragma unroll
                    for (int j2 = 0; j2 < 2; j2++)
                        mma_bf16(aU[i][jp * 2 + j2], al[i], bh[2 * j2], bh[2 * j2 + 1]);
                LDSM4T(bh, ba + 256);
                LDSM4T(bl, ba + 384);
#pragma unroll
                for (int i = 0; i < 2; i++)
#pragma unroll
                    for (int j2 = 0; j2 < 2; j2++)
                        mma_bf16(aG[i][jp * 2 + j2], ah[i], bh[2 * j2], bh[2 * j2 + 1]);
#pragma unroll
                for (int i = 0; i < 2; i++)
#pragma unroll
                    for (int j2 = 0; j2 < 2; j2++)
                        mma_bf16(aG[i][jp * 2 + j2], ah[i], bl[2 * j2], bl[2 * j2 + 1]);
#pragma unroll
                for (int i = 0; i < 2; i++)
#pragma unroll
                    for (int j2 = 0; j2 < 2; j2++)
                        mma_bf16(aG[i][jp * 2 + j2], al[i], bh[2 * j2], bh[2 * j2 + 1]);
            }
        }
        bo += S1_BUF;  if (bo == 3 * S1_BUF)  bo = 0;
        ibo += S1_BUF; if (ibo == 3 * S1_BUF) ibo = 0;
    }

    // epilogue: silu(U)*G -> inner hi/lo
    const int er = wm * 32 + (lane >> 2);
    const int ec = f0 + wn * 32 + 2 * (lane & 3);
#pragma unroll
    for (int i = 0; i < 2; i++)
#pragma unroll
        for (int half = 0; half < 2; half++) {
            int rr = er + i * 16 + half * 8;
            if (m0 + rr < cnt) {
                int id = rid_s[rr];
                size_t o = (size_t)id * FF + ec;
#pragma unroll
                for (int j = 0; j < 4; j++) {
                    float u0 = aU[i][j][half * 2 + 0], u1 = aU[i][j][half * 2 + 1];
                    float g0 = aG[i][j][half * 2 + 0], g1 = aG[i][j][half * 2 + 1];
                    float v0 = u0 / (1.f + __expf(-u0)) * g0;
                    float v1 = u1 / (1.f + __expf(-u1)) * g1;
                    uint32_t h0, l0, h1, l1;
                    splitf(v0, h0, l0); splitf(v1, h1, l1);
                    *(uint32_t*)(g_ih + o + j * 8) = h0 | (h1 << 16);
                    *(uint32_t*)(g_il + o + j * 8) = l0 | (l1 << 16);
                }
            }
        }
}

// ================= stage 2 (R10 schedule): split-K=2, no atomics =================
#define S2_BOFF 18432u
#define S2_BUF  35328u
#define SMEM2   (3 * S2_BUF)
#define S2_KC   2
#define S2_KLEN (FF / S2_KC)   // 1024

__global__ __launch_bounds__(256, 2) void stage2_mma() {
    const int e   = blockIdx.y >> 5;
    const int mt  = blockIdx.y & 31;
    const int cnt = g_count[e];
    const int m0  = mt * 128;
    if (m0 >= cnt) return;
    const int kc   = blockIdx.x & (S2_KC - 1);
    const int h0   = (blockIdx.x >> 1) * 128;
    const int tid  = threadIdx.x;
    const int lane = tid & 31;
    const int wid  = tid >> 5;
    const int wm   = wid & 3, wn = wid >> 2;

    __shared__ int rid_s[128];
    extern __shared__ char dsm[];
    const uint32_t sb = smem_u32(dsm);

    if (tid < 128) {
        int r = m0 + tid;
        rid_s[tid] = (r < cnt) ? g_plist[e * CAP + r] : 0;
    }
    __syncthreads();

    const int arow = tid >> 1, ahalf = tid & 1;
    const __nv_bfloat16* axh = g_ih + (size_t)rid_s[arow] * FF + kc * S2_KLEN + ahalf * 16;
    const __nv_bfloat16* axl = g_il + (size_t)rid_s[arow] * FF + kc * S2_KLEN + ahalf * 16;
    const uint32_t adst = sb + arow * 144 + ahalf * 32;

    const __nv_bfloat16* wdh_p = g_wdh + (size_t)e * FF * HH + (size_t)kc * S2_KLEN * HH;
    const __nv_bfloat16* wdl_p = g_wdl + (size_t)e * FF * HH + (size_t)kc * S2_KLEN * HH;
    const int b0r = tid >> 4,          b0c = (tid & 15);
    const int b1r = (tid + 256) >> 4,  b1c = (tid & 15);
    const uint32_t bdst0 = sb + S2_BOFF + b0r * 528 + b0c * 16;
    const uint32_t bdst1 = sb + S2_BOFF + b1r * 528 + b1c * 16;
    const int bcol0 = h0 + b0c * 8, bcol1 = h0 + b1c * 8;

#define S2_ISSUE(s, _bo) do {                                                  \
    int _k0 = (s) * 32;                                                        \
    uint32_t _ad = adst + (_bo);                                               \
    CP16(_ad,      axh + _k0); CP16(_ad + 16, axh + _k0 + 8);                  \
    CP16(_ad + 64, axl + _k0); CP16(_ad + 80, axl + _k0 + 8);                  \
    size_t _g0 = (size_t)(_k0 + b0r) * HH + bcol0;                             \
    size_t _g1 = (size_t)(_k0 + b1r) * HH + bcol1;                             \
    CP16(bdst0 + (_bo),       wdh_p + _g0);                                    \
    CP16(bdst0 + (_bo) + 256, wdl_p + _g0);                                    \
    CP16(bdst1 + (_bo),       wdh_p + _g1);                                    \
    CP16(bdst1 + (_bo) + 256, wdl_p + _g1);                                    \
} while (0)

    uint32_t a_base[2];
#pragma unroll
    for (int i = 0; i < 2; i++)
        a_base[i] = sb + (wm * 32 + i * 16 + (lane & 15)) * 144 + (lane >> 4) * 16;
    const uint32_t b_base = sb + S2_BOFF + (lane & 15) * 528 + (wn * 64 + (lane >> 4) * 8) * 2;

    float acc[2][8][4];
#pragma unroll
    for (int i = 0; i < 2; i++)
#pragma unroll
        for (int j = 0; j < 8; j++)
#pragma unroll
            for (int q = 0; q < 4; q++) acc[i][j][q] = 0.f;

    S2_ISSUE(0, 0u); CPCOMMIT();
    S2_ISSUE(1, S2_BUF); CPCOMMIT();

    uint32_t bo = 0, ibo = 2 * S2_BUF;
    for (int s = 0; s < S2_KLEN / 32; s++) {
        CPWAIT1();
        __syncthreads();
        if (s + 2 < S2_KLEN / 32) S2_ISSUE(s + 2, ibo);
        CPCOMMIT();
#pragma unroll
        for (int kk = 0; kk < 32; kk += 16) {
            uint32_t ah[2][4], al[2][4];
#pragma unroll
            for (int i = 0; i < 2; i++) {
                uint32_t aa = a_base[i] + bo + kk * 2;
                LDSM4(ah[i], aa);
                LDSM4(al[i], aa + 64);
            }
#pragma unroll
            for (int jq = 0; jq < 2; jq++) {
                uint32_t ba0 = b_base + bo + kk * 528 + (jq * 2) * 32;
                uint32_t bh0[4], bl0[4], bh1[4], bl1[4];
                LDSM4T(bh0, ba0);
                LDSM4T(bl0, ba0 + 256);
                LDSM4T(bh1, ba0 + 32);
                LDSM4T(bl1, ba0 + 288);
                const int j0 = jq * 4, j1 = jq * 4 + 2;
#pragma unroll
                for (int i = 0; i < 2; i++)
#pragma unroll
                    for (int j2 = 0; j2 < 2; j2++)
                        mma_bf16(acc[i][j0 + j2], ah[i], bh0[2 * j2], bh0[2 * j2 + 1]);
#pragma unroll
                for (int i = 0; i < 2; i++)
#pragma unroll
                    for (int j2 = 0; j2 < 2; j2++)
                        mma_bf16(acc[i][j1 + j2], ah[i], bh1[2 * j2], bh1[2 * j2 + 1]);
#pragma unroll
                for (int i = 0; i < 2; i++)
#pragma unroll
                    for (int j2 = 0; j2 < 2; j2++)
                        mma_bf16(acc[i][j0 + j2], ah[i], bl0[2 * j2], bl0[2 * j2 + 1]);
#pragma unroll
                for (int i = 0; i < 2; i++)
#pragma unroll
                    for (int j2 = 0; j2 < 2; j2++)
                        mma_bf16(acc[i][j1 + j2], ah[i], bl1[2 * j2], bl1[2 * j2 + 1]);
#pragma unroll
                for (int i = 0; i < 2; i++)
#pragma unroll
                    for (int j2 = 0; j2 < 2; j2++)
                        mma_bf16(acc[i][j0 + j2], al[i], bh0[2 * j2], bh0[2 * j2 + 1]);
#pragma unroll
                for (int i = 0; i < 2; i++)
#pragma unroll
                    for (int j2 = 0; j2 < 2; j2++)
                        mma_bf16(acc[i][j1 + j2], al[i], bh1[2 * j2], bh1[2 * j2 + 1]);
            }
        }
        bo += S2_BUF;  if (bo == 3 * S2_BUF)  bo = 0;
        ibo += S2_BUF; if (ibo == 3 * S2_BUF) ibo = 0;
    }

    // epilogue: weighted partials -> g_part (plain vectorized stores, no atomics)
    const int er = wm * 32 + (lane >> 2);
#pragma unroll
    for (int i = 0; i < 2; i++)
#pragma unroll
        for (int half = 0; half < 2; half++) {
            int rr = er + i * 16 + half * 8;
            if (m0 + rr < cnt) {
                int   id = rid_s[rr];
                float w  = g_wpair[id];
                float* pp = g_part + ((size_t)kc * TT * 2 + id) * HH + h0 + wn * 64 + 2 * (lane & 3);
#pragma unroll
                for (int jp = 0; jp < 4; jp++)
#pragma unroll
                    for (int j2 = 0; j2 < 2; j2++) {
                        int c = jp * 16 + j2 * 8;
                        float2 v = make_float2(w * acc[i][jp * 2 + j2][half * 2 + 0],
                                               w * acc[i][jp * 2 + j2][half * 2 + 1]);
                        *(float2*)(pp + c) = v;
                    }
            }
        }
}

// ---------------- combine: out = sum over {slot, kc}; also reset counters for NEXT run ----------------
__global__ __launch_bounds__(256) void combine_kernel(float4* __restrict__ out4) {
    int i = blockIdx.x * blockDim.x + threadIdx.x;    // < TT * HH / 4
    if (blockIdx.x == 0 && threadIdx.x < EE) g_count[threadIdx.x] = 0;
    int t  = i >> 8;                                   // HH/4 = 256
    int h4 = i & 255;
    const float4* p = (const float4*)g_part;
    size_t r00 = ((size_t)0 * TT * 2 + 2 * t)     * (HH / 4) + h4;
    size_t r01 = ((size_t)0 * TT * 2 + 2 * t + 1) * (HH / 4) + h4;
    size_t r10 = ((size_t)1 * TT * 2 + 2 * t)     * (HH / 4) + h4;
    size_t r11 = ((size_t)1 * TT * 2 + 2 * t + 1) * (HH / 4) + h4;
    float4 a = p[r00], b = p[r01], c = p[r10], d = p[r11];
    out4[i] = make_float4((a.x + b.x) + (c.x + d.x),
                          (a.y + b.y) + (c.y + d.y),
                          (a.z + b.z) + (c.z + d.z),
                          (a.w + b.w) + (c.w + d.w));
}

// ---------------- launch ----------------
extern "C" void kernel_launch(void* const* d_in, const int* in_sizes, int n_in,
                              void* d_out, int out_size) {
    const float* x  = (const float*)d_in[0];
    const float* gw = (const float*)d_in[1];
    const float* wu = (const float*)d_in[2];
    const float* wg = (const float*)d_in[3];
    const float* wd = (const float*)d_in[4];
    float* out = (float*)d_out;

    cudaFuncSetAttribute(stage1_mma, cudaFuncAttributeMaxDynamicSharedMemorySize, SMEM1);
    cudaFuncSetAttribute(stage2_mma, cudaFuncAttributeMaxDynamicSharedMemorySize, SMEM2);

    prep_kernel<<<RB + SPLIT_BLOCKS, 256>>>((const float4*)wu, (const float4*)wg,
                                            (const float4*)wd, (const float4*)x, x, gw);
    stage1_mma<<<dim3(FF / 64, EE * 32), 256, SMEM1>>>();
    stage2_mma<<<dim3((HH / 128) * S2_KC, EE * 32), 256, SMEM2>>>();
    combine_kernel<<<TT * HH / 4 / 256, 256>>>((float4*)out);
}

// round 14
// speedup vs baseline: 1.4486x; 1.3145x over previous
#include <cuda_runtime.h>
#include <cuda_fp16.h>
#include <math.h>
#include <stdint.h>

#define TT 4096
#define HH 1024
#define EE 8
#define FF 2048
#define CAP 4096
#define NW (EE * HH * FF)
#define ND (EE * FF * HH)

// ---------------- scratch ----------------
__device__ int   g_count[EE];          // zero at load; re-zeroed by combine_kernel each run
__device__ int   g_plist[EE * CAP];
__device__ float g_wpair[TT * 2];
__device__ __align__(16) __half g_xh[TT * HH], g_xl[TT * HH];     // x fp16 pair
__device__ __align__(16) __half g_wuh[NW];                         // weights: fp16 hi only
__device__ __align__(16) __half g_wgh[NW];
__device__ __align__(16) __half g_wdh[ND];
__device__ __align__(16) __half g_ih[(size_t)TT * 2 * FF], g_il[(size_t)TT * 2 * FF];
__device__ __align__(16) float g_part[(size_t)2 * TT * 2 * HH];   // 67 MB

// ---------------- helpers ----------------
__device__ __forceinline__ uint32_t smem_u32(const void* p) {
    uint32_t a;
    asm("{ .reg .u64 t; cvta.to.shared.u64 t, %1; cvt.u32.u64 %0, t; }" : "=r"(a) : "l"(p));
    return a;
}
__device__ __forceinline__ void splith(float f, uint32_t& h, uint32_t& l) {
    __half hb = __float2half_rn(f);
    float rf = f - __half2float(hb);
    __half lb = __float2half_rn(rf);
    h = (uint32_t)__half_as_ushort(hb);
    l = (uint32_t)__half_as_ushort(lb);
}
__device__ __forceinline__ uint32_t h16(float f) {
    return (uint32_t)__half_as_ushort(__float2half_rn(f));
}

#define CP16(dst, src)  asm volatile("cp.async.cg.shared.global [%0], [%1], 16;" :: "r"(dst), "l"(src))
#define CPCOMMIT()      asm volatile("cp.async.commit_group;" ::: "memory")
#define CPWAIT1()       asm volatile("cp.async.wait_group 1;" ::: "memory")

#define LDSM4(r, a)                                                                   \
    asm volatile("ldmatrix.sync.aligned.m8n8.x4.shared.b16 {%0,%1,%2,%3}, [%4];"      \
        : "=r"((r)[0]), "=r"((r)[1]), "=r"((r)[2]), "=r"((r)[3]) : "r"(a))
#define LDSM4T(r, a)                                                                  \
    asm volatile("ldmatrix.sync.aligned.m8n8.x4.trans.shared.b16 {%0,%1,%2,%3}, [%4];"\
        : "=r"((r)[0]), "=r"((r)[1]), "=r"((r)[2]), "=r"((r)[3]) : "r"(a))

__device__ __forceinline__ void mma_f16(float* d, const uint32_t* a, uint32_t b0, uint32_t b1) {
    asm volatile(
        "mma.sync.aligned.m16n8k16.row.col.f32.f16.f16.f32 "
        "{%0,%1,%2,%3},{%4,%5,%6,%7},{%8,%9},{%0,%1,%2,%3};"
        : "+f"(d[0]), "+f"(d[1]), "+f"(d[2]), "+f"(d[3])
        : "r"(a[0]), "r"(a[1]), "r"(a[2]), "r"(a[3]), "r"(b0), "r"(b1));
}

// ---------------- fused prep: router (first RB blocks) + split (rest) ----------------
#define NW4 (NW / 4)
#define NX4 (TT * HH / 4)
#define RB  (TT / 8)
#define SPLIT_BLOCKS ((3 * NW4 + NX4) / 256)

__global__ __launch_bounds__(256) void prep_kernel(const float4* __restrict__ wu,
                                                   const float4* __restrict__ wg,
                                                   const float4* __restrict__ wd,
                                                   const float4* __restrict__ x4,
                                                   const float*  __restrict__ xf,
                                                   const float*  __restrict__ gwf) {
    if (blockIdx.x < RB) {
        // ---- router: warp per token; fp32 products, fp64 group accumulation ----
        const int warp = threadIdx.x >> 5, lane = threadIdx.x & 31;
        const int t = blockIdx.x * 8 + warp;
        const float* xp = xf + (size_t)t * HH;

        double acc[EE];
#pragma unroll
        for (int e = 0; e < EE; e++) acc[e] = 0.0;
#pragma unroll
        for (int g = 0; g < 4; g++) {
            float p[EE];
#pragma unroll
            for (int e = 0; e < EE; e++) p[e] = 0.f;
#pragma unroll
            for (int j8 = 0; j8 < 8; j8++) {
                int h = lane + 32 * (g * 8 + j8);
                float xv = xp[h];
                float4 w0 = *(const float4*)(gwf + h * EE);
                float4 w1 = *(const float4*)(gwf + h * EE + 4);
                p[0] += xv * w0.x; p[1] += xv * w0.y;
                p[2] += xv * w0.z; p[3] += xv * w0.w;
                p[4] += xv * w1.x; p[5] += xv * w1.y;
                p[6] += xv * w1.z; p[7] += xv * w1.w;
            }
#pragma unroll
            for (int e = 0; e < EE; e++) acc[e] += (double)p[e];
        }
#pragma unroll
        for (int off = 16; off > 0; off >>= 1)
#pragma unroll
            for (int e = 0; e < EE; e++)
                acc[e] += __shfl_down_sync(0xffffffffu, acc[e], off);

        if (lane == 0) {
            int i0 = 0;
            for (int e = 1; e < EE; e++) if (acc[e] > acc[i0]) i0 = e;
            int i1 = (i0 == 0) ? 1 : 0;
            for (int e = 0; e < EE; e++) if (e != i0 && acc[e] > acc[i1]) i1 = e;
            double d  = exp(acc[i1] - acc[i0]);
            float  w0 = (float)(1.0 / (1.0 + d));
            float  w1 = (float)(d / (1.0 + d));
            int p0 = atomicAdd(&g_count[i0], 1);
            g_plist[i0 * CAP + p0] = t * 2;
            int p1 = atomicAdd(&g_count[i1], 1);
            g_plist[i1 * CAP + p1] = t * 2 + 1;
            g_wpair[t * 2]     = w0;
            g_wpair[t * 2 + 1] = w1;
        }
        return;
    }

    // ---- split ----
    int i = (blockIdx.x - RB) * blockDim.x + threadIdx.x;
    if (i < 3 * NW4) {
        // weights: fp16 hi plane only
        const float4* src;
        __half* hp;
        int j;
        if (i < NW4)          { src = wu; hp = g_wuh; j = i; }
        else if (i < 2 * NW4) { src = wg; hp = g_wgh; j = i - NW4; }
        else                  { src = wd; hp = g_wdh; j = i - 2 * NW4; }
        float4 v = src[j];
        uint32_t h0 = h16(v.x), h1 = h16(v.y), h2 = h16(v.z), h3 = h16(v.w);
        ((uint2*)hp)[j] = make_uint2(h0 | (h1 << 16), h2 | (h3 << 16));
    } else if (i < 3 * NW4 + NX4) {
        // x: fp16 hi/lo pair
        int j = i - 3 * NW4;
        float4 v = x4[j];
        uint32_t h0, h1, h2, h3, l0, l1, l2, l3;
        splith(v.x, h0, l0); splith(v.y, h1, l1);
        splith(v.z, h2, l2); splith(v.w, h3, l3);
        ((uint2*)g_xh)[j] = make_uint2(h0 | (h1 << 16), h2 | (h3 << 16));
        ((uint2*)g_xl)[j] = make_uint2(l0 | (l1 << 16), l2 | (l3 << 16));
    }
}

// ================= stage 1: inner = silu(X@Wup) * (X@Wgate)  (fp16, 2 MMAs/result) =================
// BM=128, BN=64, BK=32. 8 warps = 4m x 2n, warp 32x32 (dual U/G acc).
// A rows 144B (hi 64 | lo 64 | pad 16), 128 rows = 18432.
// B rows 272B (Uh 128 | Gh 128 | pad 16), 32 rows = 8704.
#define S1_BOFF 18432u
#define S1_BUF  27136u
#define SMEM1   (3 * S1_BUF)

__global__ __launch_bounds__(256, 2) void stage1_mma() {
    const int e   = blockIdx.y >> 5;
    const int mt  = blockIdx.y & 31;
    const int cnt = g_count[e];
    const int m0  = mt * 128;
    if (m0 >= cnt) return;
    const int f0   = blockIdx.x * 64;
    const int tid  = threadIdx.x;
    const int lane = tid & 31;
    const int wid  = tid >> 5;
    const int wm   = wid & 3, wn = wid >> 2;

    __shared__ int rid_s[128];
    extern __shared__ char dsm[];
    const uint32_t sb = smem_u32(dsm);

    if (tid < 128) {
        int r = m0 + tid;
        rid_s[tid] = (r < cnt) ? g_plist[e * CAP + r] : 0;
    }
    __syncthreads();

    const int arow = tid >> 1, ahalf = tid & 1;
    const __half* axh = g_xh + (size_t)(rid_s[arow] >> 1) * HH + ahalf * 16;
    const __half* axl = g_xl + (size_t)(rid_s[arow] >> 1) * HH + ahalf * 16;
    const uint32_t adst = sb + arow * 144 + ahalf * 32;

    // B: 32 rows x (Uh|Gh) 16B chunks: 8 segs/row/plane; 256 threads -> 1 chunk/plane each
    const int brow = tid >> 3, bseg = tid & 7;
    const __half* wuh_p = g_wuh + (size_t)e * HH * FF;
    const __half* wgh_p = g_wgh + (size_t)e * HH * FF;
    const uint32_t bdst = sb + S1_BOFF + brow * 272 + bseg * 16;
    const int bcol8 = f0 + bseg * 8;

#define S1_ISSUE(s, _bo) do {                                                  \
    int _k0 = (s) * 32;                                                        \
    uint32_t _ad = adst + (_bo);                                               \
    CP16(_ad,      axh + _k0); CP16(_ad + 16, axh + _k0 + 8);                  \
    CP16(_ad + 64, axl + _k0); CP16(_ad + 80, axl + _k0 + 8);                  \
    size_t _go = (size_t)(_k0 + brow) * FF + bcol8;                            \
    uint32_t _bd = bdst + (_bo);                                               \
    CP16(_bd,       wuh_p + _go);                                              \
    CP16(_bd + 128, wgh_p + _go);                                              \
} while (0)

    uint32_t a_base[2];
#pragma unroll
    for (int i = 0; i < 2; i++)
        a_base[i] = sb + (wm * 32 + i * 16 + (lane & 15)) * 144 + (lane >> 4) * 16;
    const uint32_t b_base = sb + S1_BOFF + (lane & 15) * 272 + (wn * 32 + (lane >> 4) * 8) * 2;

    float aU[2][4][4], aG[2][4][4];
#pragma unroll
    for (int i = 0; i < 2; i++)
#pragma unroll
        for (int j = 0; j < 4; j++)
#pragma unroll
            for (int q = 0; q < 4; q++) { aU[i][j][q] = 0.f; aG[i][j][q] = 0.f; }

    S1_ISSUE(0, 0u); CPCOMMIT();
    S1_ISSUE(1, S1_BUF); CPCOMMIT();

    uint32_t bo = 0, ibo = 2 * S1_BUF;
    for (int s = 0; s < 32; s++) {
        CPWAIT1();
        __syncthreads();
        if (s + 2 < 32) S1_ISSUE(s + 2, ibo);
        CPCOMMIT();
#pragma unroll
        for (int kk = 0; kk < 32; kk += 16) {
            uint32_t ah[2][4], al[2][4];
#pragma unroll
            for (int i = 0; i < 2; i++) {
                uint32_t aa = a_base[i] + bo + kk * 2;
                LDSM4(ah[i], aa);
                LDSM4(al[i], aa + 64);
            }
#pragma unroll
            for (int jp = 0; jp < 2; jp++) {
                uint32_t ba = b_base + bo + kk * 272 + jp * 32;
                uint32_t bhU[4], bhG[4];
                LDSM4T(bhU, ba);
                LDSM4T(bhG, ba + 128);
                // hh: U then G, then lh: U then G -> RAW distance 8
#pragma unroll
                for (int i = 0; i < 2; i++)
#pragma unroll
                    for (int j2 = 0; j2 < 2; j2++)
                        mma_f16(aU[i][jp * 2 + j2], ah[i], bhU[2 * j2], bhU[2 * j2 + 1]);
#pragma unroll
                for (int i = 0; i < 2; i++)
#pragma unroll
                    for (int j2 = 0; j2 < 2; j2++)
                        mma_f16(aG[i][jp * 2 + j2], ah[i], bhG[2 * j2], bhG[2 * j2 + 1]);
#pragma unroll
                for (int i = 0; i < 2; i++)
#pragma unroll
                    for (int j2 = 0; j2 < 2; j2++)
                        mma_f16(aU[i][jp * 2 + j2], al[i], bhU[2 * j2], bhU[2 * j2 + 1]);
#pragma unroll
                for (int i = 0; i < 2; i++)
#pragma unroll
                    for (int j2 = 0; j2 < 2; j2++)
                        mma_f16(aG[i][jp * 2 + j2], al[i], bhG[2 * j2], bhG[2 * j2 + 1]);
            }
        }
        bo += S1_BUF;  if (bo == 3 * S1_BUF)  bo = 0;
        ibo += S1_BUF; if (ibo == 3 * S1_BUF) ibo = 0;
    }

    // epilogue: silu(U)*G -> inner fp16 hi/lo
    const int er = wm * 32 + (lane >> 2);
    const int ec = f0 + wn * 32 + 2 * (lane & 3);
#pragma unroll
    for (int i = 0; i < 2; i++)
#pragma unroll
        for (int half = 0; half < 2; half++) {
            int rr = er + i * 16 + half * 8;
            if (m0 + rr < cnt) {
                int id = rid_s[rr];
                size_t o = (size_t)id * FF + ec;
#pragma unroll
                for (int j = 0; j < 4; j++) {
                    float u0 = aU[i][j][half * 2 + 0], u1 = aU[i][j][half * 2 + 1];
                    float g0 = aG[i][j][half * 2 + 0], g1 = aG[i][j][half * 2 + 1];
                    float v0 = u0 / (1.f + __expf(-u0)) * g0;
                    float v1 = u1 / (1.f + __expf(-u1)) * g1;
                    uint32_t h0, l0, h1, l1;
                    splith(v0, h0, l0); splith(v1, h1, l1);
                    *(uint32_t*)(g_ih + o + j * 8) = h0 | (h1 << 16);
                    *(uint32_t*)(g_il + o + j * 8) = l0 | (l1 << 16);
                }
            }
        }
}

// ================= stage 2: split-K=2, no atomics (fp16, 2 MMAs/result) =================
// BM=128, BN=128, BK=32, 32 k-steps per block. 8 warps = 4m x 2n, warp 32x64.
// A rows 144B (hi 64 | lo 64 | pad 16), 128 rows = 18432.
// B rows 272B (hi 256 | pad 16), 32 rows = 8704.
#define S2_BOFF 18432u
#define S2_BUF  27136u
#define SMEM2   (3 * S2_BUF)
#define S2_KC   2
#define S2_KLEN (FF / S2_KC)   // 1024

__global__ __launch_bounds__(256, 2) void stage2_mma() {
    const int e   = blockIdx.y >> 5;
    const int mt  = blockIdx.y & 31;
    const int cnt = g_count[e];
    const int m0  = mt * 128;
    if (m0 >= cnt) return;
    const int kc   = blockIdx.x & (S2_KC - 1);
    const int h0   = (blockIdx.x >> 1) * 128;
    const int tid  = threadIdx.x;
    const int lane = tid & 31;
    const int wid  = tid >> 5;
    const int wm   = wid & 3, wn = wid >> 2;

    __shared__ int rid_s[128];
    extern __shared__ char dsm[];
    const uint32_t sb = smem_u32(dsm);

    if (tid < 128) {
        int r = m0 + tid;
        rid_s[tid] = (r < cnt) ? g_plist[e * CAP + r] : 0;
    }
    __syncthreads();

    const int arow = tid >> 1, ahalf = tid & 1;
    const __half* axh = g_ih + (size_t)rid_s[arow] * FF + kc * S2_KLEN + ahalf * 16;
    const __half* axl = g_il + (size_t)rid_s[arow] * FF + kc * S2_KLEN + ahalf * 16;
    const uint32_t adst = sb + arow * 144 + ahalf * 32;

    // B: 32 rows x 128 cols fp16 = 256B/row = 16 chunks of 16B; 512 chunks; 2 per thread
    const __half* wdh_p = g_wdh + (size_t)e * FF * HH + (size_t)kc * S2_KLEN * HH;
    const int b0r = tid >> 4,          b0c = (tid & 15);
    const int b1r = (tid + 256) >> 4,  b1c = (tid & 15);
    const uint32_t bdst0 = sb + S2_BOFF + b0r * 272 + b0c * 16;
    const uint32_t bdst1 = sb + S2_BOFF + b1r * 272 + b1c * 16;
    const int bcol0 = h0 + b0c * 8, bcol1 = h0 + b1c * 8;

#define S2_ISSUE(s, _bo) do {                                                  \
    int _k0 = (s) * 32;                                                        \
    uint32_t _ad = adst + (_bo);                                               \
    CP16(_ad,      axh + _k0); CP16(_ad + 16, axh + _k0 + 8);                  \
    CP16(_ad + 64, axl + _k0); CP16(_ad + 80, axl + _k0 + 8);                  \
    size_t _g0 = (size_t)(_k0 + b0r) * HH + bcol0;                             \
    size_t _g1 = (size_t)(_k0 + b1r) * HH + bcol1;                             \
    CP16(bdst0 + (_bo), wdh_p + _g0);                                          \
    CP16(bdst1 + (_bo), wdh_p + _g1);                                          \
} while (0)

    uint32_t a_base[2];
#pragma unroll
    for (int i = 0; i < 2; i++)
        a_base[i] = sb + (wm * 32 + i * 16 + (lane & 15)) * 144 + (lane >> 4) * 16;
    const uint32_t b_base = sb + S2_BOFF + (lane & 15) * 272 + (wn * 64 + (lane >> 4) * 8) * 2;

    float acc[2][8][4];
#pragma unroll
    for (int i = 0; i < 2; i++)
#pragma unroll
        for (int j = 0; j < 8; j++)
#pragma unroll
            for (int q = 0; q < 4; q++) acc[i][j][q] = 0.f;

    S2_ISSUE(0, 0u); CPCOMMIT();
    S2_ISSUE(1, S2_BUF); CPCOMMIT();

    uint32_t bo = 0, ibo = 2 * S2_BUF;
    for (int s = 0; s < S2_KLEN / 32; s++) {
        CPWAIT1();
        __syncthreads();
        if (s + 2 < S2_KLEN / 32) S2_ISSUE(s + 2, ibo);
        CPCOMMIT();
#pragma unroll
        for (int kk = 0; kk < 32; kk += 16) {
            uint32_t ah[2][4], al[2][4];
#pragma unroll
            for (int i = 0; i < 2; i++) {
                uint32_t aa = a_base[i] + bo + kk * 2;
                LDSM4(ah[i], aa);
                LDSM4(al[i], aa + 64);
            }
#pragma unroll
            for (int jq = 0; jq < 2; jq++) {
                uint32_t ba0 = b_base + bo + kk * 272 + jq * 64;
                uint32_t bh0[4], bh1[4];
                LDSM4T(bh0, ba0);
                LDSM4T(bh1, ba0 + 32);
                const int j0 = jq * 4, j1 = jq * 4 + 2;
                // hh across jp pair, then lh across pair -> RAW distance 8
#pragma unroll
                for (int i = 0; i < 2; i++)
#pragma unroll
                    for (int j2 = 0; j2 < 2; j2++)
                        mma_f16(acc[i][j0 + j2], ah[i], bh0[2 * j2], bh0[2 * j2 + 1]);
#pragma unroll
                for (int i = 0; i < 2; i++)
#pragma unroll
                    for (int j2 = 0; j2 < 2; j2++)
                        mma_f16(acc[i][j1 + j2], ah[i], bh1[2 * j2], bh1[2 * j2 + 1]);
#pragma unroll
                for (int i = 0; i < 2; i++)
#pragma unroll
                    for (int j2 = 0; j2 < 2; j2++)
                        mma_f16(acc[i][j0 + j2], al[i], bh0[2 * j2], bh0[2 * j2 + 1]);
#pragma unroll
                for (int i = 0; i < 2; i++)
#pragma unroll
                    for (int j2 = 0; j2 < 2; j2++)
                        mma_f16(acc[i][j1 + j2], al[i], bh1[2 * j2], bh1[2 * j2 + 1]);
            }
        }
        bo += S2_BUF;  if (bo == 3 * S2_BUF)  bo = 0;
        ibo += S2_BUF; if (ibo == 3 * S2_BUF) ibo = 0;
    }

    // epilogue: weighted partials -> g_part (plain vectorized stores, no atomics)
    const int er = wm * 32 + (lane >> 2);
#pragma unroll
    for (int i = 0; i < 2; i++)
#pragma unroll
        for (int half = 0; half < 2; half++) {
            int rr = er + i * 16 + half * 8;
            if (m0 + rr < cnt) {
                int   id = rid_s[rr];
                float w  = g_wpair[id];
                float* pp = g_part + ((size_t)kc * TT * 2 + id) * HH + h0 + wn * 64 + 2 * (lane & 3);
#pragma unroll
                for (int jp = 0; jp < 4; jp++)
#pragma unroll
                    for (int j2 = 0; j2 < 2; j2++) {
                        int c = jp * 16 + j2 * 8;
                        float2 v = make_float2(w * acc[i][jp * 2 + j2][half * 2 + 0],
                                               w * acc[i][jp * 2 + j2][half * 2 + 1]);
                        *(float2*)(pp + c) = v;
                    }
            }
        }
}

// ---------------- combine: out = sum over {slot, kc}; reset counters for NEXT run ----------------
__global__ __launch_bounds__(256) void combine_kernel(float4* __restrict__ out4) {
    int i = blockIdx.x * blockDim.x + threadIdx.x;
    if (blockIdx.x == 0 && threadIdx.x < EE) g_count[threadIdx.x] = 0;
    int t  = i >> 8;
    int h4 = i & 255;
    const float4* p = (const float4*)g_part;
    size_t r00 = ((size_t)0 * TT * 2 + 2 * t)     * (HH / 4) + h4;
    size_t r01 = ((size_t)0 * TT * 2 + 2 * t + 1) * (HH / 4) + h4;
    size_t r10 = ((size_t)1 * TT * 2 + 2 * t)     * (HH / 4) + h4;
    size_t r11 = ((size_t)1 * TT * 2 + 2 * t + 1) * (HH / 4) + h4;
    float4 a = p[r00], b = p[r01], c = p[r10], d = p[r11];
    out4[i] = make_float4((a.x + b.x) + (c.x + d.x),
                          (a.y + b.y) + (c.y + d.y),
                          (a.z + b.z) + (c.z + d.z),
                          (a.w + b.w) + (c.w + d.w));
}

// ---------------- launch ----------------
extern "C" void kernel_launch(void* const* d_in, const int* in_sizes, int n_in,
                              void* d_out, int out_size) {
    const float* x  = (const float*)d_in[0];
    const float* gw = (const float*)d_in[1];
    const float* wu = (const float*)d_in[2];
    const float* wg = (const float*)d_in[3];
    const float* wd = (const float*)d_in[4];
    float* out = (float*)d_out;

    cudaFuncSetAttribute(stage1_mma, cudaFuncAttributeMaxDynamicSharedMemorySize, SMEM1);
    cudaFuncSetAttribute(stage2_mma, cudaFuncAttributeMaxDynamicSharedMemorySize, SMEM2);

    prep_kernel<<<RB + SPLIT_BLOCKS, 256>>>((const float4*)wu, (const float4*)wg,
                                            (const float4*)wd, (const float4*)x, x, gw);
    stage1_mma<<<dim3(FF / 64, EE * 32), 256, SMEM1>>>();
    stage2_mma<<<dim3((HH / 128) * S2_KC, EE * 32), 256, SMEM2>>>();
    combine_kernel<<<TT * HH / 4 / 256, 256>>>((float4*)out);
}

// round 15
// speedup vs baseline: 2.1087x; 1.4557x over previous
#include <cuda_runtime.h>
#include <cuda_fp16.h>
#include <math.h>
#include <stdint.h>

#define TT 4096
#define HH 1024
#define EE 8
#define FF 2048
#define CAP 4096
#define NW (EE * HH * FF)
#define ND (EE * FF * HH)

// ---------------- scratch ----------------
__device__ int   g_count[EE];          // zero at load; re-zeroed by combine_kernel each run
__device__ int   g_plist[EE * CAP];
__device__ float g_wpair[TT * 2];
__device__ __align__(16) __half g_xh[TT * HH];                    // x fp16 (single)
__device__ __align__(16) __half g_wuh[NW];
__device__ __align__(16) __half g_wgh[NW];
__device__ __align__(16) __half g_wdh[ND];
__device__ __align__(16) __half g_ih[(size_t)TT * 2 * FF];        // inner fp16 (single)
__device__ __align__(16) float g_part[(size_t)2 * TT * 2 * HH];   // 67 MB

// ---------------- helpers ----------------
__device__ __forceinline__ uint32_t smem_u32(const void* p) {
    uint32_t a;
    asm("{ .reg .u64 t; cvta.to.shared.u64 t, %1; cvt.u32.u64 %0, t; }" : "=r"(a) : "l"(p));
    return a;
}
__device__ __forceinline__ uint32_t h16(float f) {
    return (uint32_t)__half_as_ushort(__float2half_rn(f));
}

#define CP16(dst, src)  asm volatile("cp.async.cg.shared.global [%0], [%1], 16;" :: "r"(dst), "l"(src))
#define CPCOMMIT()      asm volatile("cp.async.commit_group;" ::: "memory")
#define CPWAIT1()       asm volatile("cp.async.wait_group 1;" ::: "memory")

#define LDSM4(r, a)                                                                   \
    asm volatile("ldmatrix.sync.aligned.m8n8.x4.shared.b16 {%0,%1,%2,%3}, [%4];"      \
        : "=r"((r)[0]), "=r"((r)[1]), "=r"((r)[2]), "=r"((r)[3]) : "r"(a))
#define LDSM4T(r, a)                                                                  \
    asm volatile("ldmatrix.sync.aligned.m8n8.x4.trans.shared.b16 {%0,%1,%2,%3}, [%4];"\
        : "=r"((r)[0]), "=r"((r)[1]), "=r"((r)[2]), "=r"((r)[3]) : "r"(a))

__device__ __forceinline__ void mma_f16(float* d, const uint32_t* a, uint32_t b0, uint32_t b1) {
    asm volatile(
        "mma.sync.aligned.m16n8k16.row.col.f32.f16.f16.f32 "
        "{%0,%1,%2,%3},{%4,%5,%6,%7},{%8,%9},{%0,%1,%2,%3};"
        : "+f"(d[0]), "+f"(d[1]), "+f"(d[2]), "+f"(d[3])
        : "r"(a[0]), "r"(a[1]), "r"(a[2]), "r"(a[3]), "r"(b0), "r"(b1));
}

// ---------------- fused prep: router (first RB blocks) + split (rest) ----------------
#define NW4 (NW / 4)
#define NX4 (TT * HH / 4)
#define RB  (TT / 8)
#define SPLIT_BLOCKS ((3 * NW4 + NX4) / 256)

__global__ __launch_bounds__(256) void prep_kernel(const float4* __restrict__ wu,
                                                   const float4* __restrict__ wg,
                                                   const float4* __restrict__ wd,
                                                   const float4* __restrict__ x4,
                                                   const float*  __restrict__ xf,
                                                   const float*  __restrict__ gwf) {
    if (blockIdx.x < RB) {
        // ---- router: warp per token; fp32 products, fp64 group accumulation ----
        const int warp = threadIdx.x >> 5, lane = threadIdx.x & 31;
        const int t = blockIdx.x * 8 + warp;
        const float* xp = xf + (size_t)t * HH;

        double acc[EE];
#pragma unroll
        for (int e = 0; e < EE; e++) acc[e] = 0.0;
#pragma unroll
        for (int g = 0; g < 4; g++) {
            float p[EE];
#pragma unroll
            for (int e = 0; e < EE; e++) p[e] = 0.f;
#pragma unroll
            for (int j8 = 0; j8 < 8; j8++) {
                int h = lane + 32 * (g * 8 + j8);
                float xv = xp[h];
                float4 w0 = *(const float4*)(gwf + h * EE);
                float4 w1 = *(const float4*)(gwf + h * EE + 4);
                p[0] += xv * w0.x; p[1] += xv * w0.y;
                p[2] += xv * w0.z; p[3] += xv * w0.w;
                p[4] += xv * w1.x; p[5] += xv * w1.y;
                p[6] += xv * w1.z; p[7] += xv * w1.w;
            }
#pragma unroll
            for (int e = 0; e < EE; e++) acc[e] += (double)p[e];
        }
#pragma unroll
        for (int off = 16; off > 0; off >>= 1)
#pragma unroll
            for (int e = 0; e < EE; e++)
                acc[e] += __shfl_down_sync(0xffffffffu, acc[e], off);

        if (lane == 0) {
            int i0 = 0;
            for (int e = 1; e < EE; e++) if (acc[e] > acc[i0]) i0 = e;
            int i1 = (i0 == 0) ? 1 : 0;
            for (int e = 0; e < EE; e++) if (e != i0 && acc[e] > acc[i1]) i1 = e;
            double d  = exp(acc[i1] - acc[i0]);
            float  w0 = (float)(1.0 / (1.0 + d));
            float  w1 = (float)(d / (1.0 + d));
            int p0 = atomicAdd(&g_count[i0], 1);
            g_plist[i0 * CAP + p0] = t * 2;
            int p1 = atomicAdd(&g_count[i1], 1);
            g_plist[i1 * CAP + p1] = t * 2 + 1;
            g_wpair[t * 2]     = w0;
            g_wpair[t * 2 + 1] = w1;
        }
        return;
    }

    // ---- split: fp32 -> fp16 (single plane) ----
    int i = (blockIdx.x - RB) * blockDim.x + threadIdx.x;
    const float4* src;
    __half* hp;
    int j;
    if (i < NW4)               { src = wu; hp = g_wuh; j = i; }
    else if (i < 2 * NW4)      { src = wg; hp = g_wgh; j = i - NW4; }
    else if (i < 3 * NW4)      { src = wd; hp = g_wdh; j = i - 2 * NW4; }
    else if (i < 3 * NW4 + NX4){ src = x4; hp = g_xh;  j = i - 3 * NW4; }
    else return;
    float4 v = src[j];
    uint32_t h0 = h16(v.x), h1 = h16(v.y), h2 = h16(v.z), h3 = h16(v.w);
    ((uint2*)hp)[j] = make_uint2(h0 | (h1 << 16), h2 | (h3 << 16));
}

// ================= stage 1: inner = silu(X@Wup) * (X@Wgate)  (fp16, 1 MMA/result) =================
// BM=128, BN=64, BK=32. 8 warps = 4m x 2n, warp 32x32 (dual U/G acc).
// A rows 80B (64 data | 16 pad), 128 rows = 10240.
// B rows 272B (Uh 128 | Gh 128 | pad 16), 32 rows = 8704.
#define S1_BOFF 10240u
#define S1_BUF  18944u
#define SMEM1   (3 * S1_BUF)

__global__ __launch_bounds__(256, 2) void stage1_mma() {
    const int e   = blockIdx.y >> 5;
    const int mt  = blockIdx.y & 31;
    const int cnt = g_count[e];
    const int m0  = mt * 128;
    if (m0 >= cnt) return;
    const int f0   = blockIdx.x * 64;
    const int tid  = threadIdx.x;
    const int lane = tid & 31;
    const int wid  = tid >> 5;
    const int wm   = wid & 3, wn = wid >> 2;

    __shared__ int rid_s[128];
    extern __shared__ char dsm[];
    const uint32_t sb = smem_u32(dsm);

    if (tid < 128) {
        int r = m0 + tid;
        rid_s[tid] = (r < cnt) ? g_plist[e * CAP + r] : 0;
    }
    __syncthreads();

    const int arow = tid >> 1, ahalf = tid & 1;
    const __half* axh = g_xh + (size_t)(rid_s[arow] >> 1) * HH + ahalf * 16;
    const uint32_t adst = sb + arow * 80 + ahalf * 32;

    const int brow = tid >> 3, bseg = tid & 7;
    const __half* wuh_p = g_wuh + (size_t)e * HH * FF;
    const __half* wgh_p = g_wgh + (size_t)e * HH * FF;
    const uint32_t bdst = sb + S1_BOFF + brow * 272 + bseg * 16;
    const int bcol8 = f0 + bseg * 8;

#define S1_ISSUE(s, _bo) do {                                                  \
    int _k0 = (s) * 32;                                                        \
    uint32_t _ad = adst + (_bo);                                               \
    CP16(_ad,      axh + _k0); CP16(_ad + 16, axh + _k0 + 8);                  \
    size_t _go = (size_t)(_k0 + brow) * FF + bcol8;                            \
    uint32_t _bd = bdst + (_bo);                                               \
    CP16(_bd,       wuh_p + _go);                                              \
    CP16(_bd + 128, wgh_p + _go);                                              \
} while (0)

    uint32_t a_base[2];
#pragma unroll
    for (int i = 0; i < 2; i++)
        a_base[i] = sb + (wm * 32 + i * 16 + (lane & 15)) * 80 + (lane >> 4) * 16;
    const uint32_t b_base = sb + S1_BOFF + (lane & 15) * 272 + (wn * 32 + (lane >> 4) * 8) * 2;

    float aU[2][4][4], aG[2][4][4];
#pragma unroll
    for (int i = 0; i < 2; i++)
#pragma unroll
        for (int j = 0; j < 4; j++)
#pragma unroll
            for (int q = 0; q < 4; q++) { aU[i][j][q] = 0.f; aG[i][j][q] = 0.f; }

    S1_ISSUE(0, 0u); CPCOMMIT();
    S1_ISSUE(1, S1_BUF); CPCOMMIT();

    uint32_t bo = 0, ibo = 2 * S1_BUF;
    for (int s = 0; s < 32; s++) {
        CPWAIT1();
        __syncthreads();
        if (s + 2 < 32) S1_ISSUE(s + 2, ibo);
        CPCOMMIT();
#pragma unroll
        for (int kk = 0; kk < 32; kk += 16) {
            uint32_t ah[2][4];
#pragma unroll
            for (int i = 0; i < 2; i++)
                LDSM4(ah[i], a_base[i] + bo + kk * 2);
#pragma unroll
            for (int jp = 0; jp < 2; jp++) {
                uint32_t ba = b_base + bo + kk * 272 + jp * 32;
                uint32_t bhU[4], bhG[4];
                LDSM4T(bhU, ba);
                LDSM4T(bhG, ba + 128);
#pragma unroll
                for (int i = 0; i < 2; i++)
#pragma unroll
                    for (int j2 = 0; j2 < 2; j2++)
                        mma_f16(aU[i][jp * 2 + j2], ah[i], bhU[2 * j2], bhU[2 * j2 + 1]);
#pragma unroll
                for (int i = 0; i < 2; i++)
#pragma unroll
                    for (int j2 = 0; j2 < 2; j2++)
                        mma_f16(aG[i][jp * 2 + j2], ah[i], bhG[2 * j2], bhG[2 * j2 + 1]);
            }
        }
        bo += S1_BUF;  if (bo == 3 * S1_BUF)  bo = 0;
        ibo += S1_BUF; if (ibo == 3 * S1_BUF) ibo = 0;
    }

    // epilogue: silu(U)*G -> inner fp16
    const int er = wm * 32 + (lane >> 2);
    const int ec = f0 + wn * 32 + 2 * (lane & 3);
#pragma unroll
    for (int i = 0; i < 2; i++)
#pragma unroll
        for (int half = 0; half < 2; half++) {
            int rr = er + i * 16 + half * 8;
            if (m0 + rr < cnt) {
                int id = rid_s[rr];
                size_t o = (size_t)id * FF + ec;
#pragma unroll
                for (int j = 0; j < 4; j++) {
                    float u0 = aU[i][j][half * 2 + 0], u1 = aU[i][j][half * 2 + 1];
                    float g0 = aG[i][j][half * 2 + 0], g1 = aG[i][j][half * 2 + 1];
                    float v0 = u0 / (1.f + __expf(-u0)) * g0;
                    float v1 = u1 / (1.f + __expf(-u1)) * g1;
                    *(uint32_t*)(g_ih + o + j * 8) = h16(v0) | (h16(v1) << 16);
                }
            }
        }
}

// ================= stage 2: split-K=2, no atomics (fp16, 1 MMA/result) =================
// BM=128, BN=128, BK=32, 32 k-steps per block. 8 warps = 4m x 2n, warp 32x64.
// A rows 80B, 128 rows = 10240.  B rows 272B (256 data | 16 pad), 32 rows = 8704.
#define S2_BOFF 10240u
#define S2_BUF  18944u
#define SMEM2   (3 * S2_BUF)
#define S2_KC   2
#define S2_KLEN (FF / S2_KC)   // 1024

__global__ __launch_bounds__(256, 2) void stage2_mma() {
    const int e   = blockIdx.y >> 5;
    const int mt  = blockIdx.y & 31;
    const int cnt = g_count[e];
    const int m0  = mt * 128;
    if (m0 >= cnt) return;
    const int kc   = blockIdx.x & (S2_KC - 1);
    const int h0   = (blockIdx.x >> 1) * 128;
    const int tid  = threadIdx.x;
    const int lane = tid & 31;
    const int wid  = tid >> 5;
    const int wm   = wid & 3, wn = wid >> 2;

    __shared__ int rid_s[128];
    extern __shared__ char dsm[];
    const uint32_t sb = smem_u32(dsm);

    if (tid < 128) {
        int r = m0 + tid;
        rid_s[tid] = (r < cnt) ? g_plist[e * CAP + r] : 0;
    }
    __syncthreads();

    const int arow = tid >> 1, ahalf = tid & 1;
    const __half* axh = g_ih + (size_t)rid_s[arow] * FF + kc * S2_KLEN + ahalf * 16;
    const uint32_t adst = sb + arow * 80 + ahalf * 32;

    const __half* wdh_p = g_wdh + (size_t)e * FF * HH + (size_t)kc * S2_KLEN * HH;
    const int b0r = tid >> 4,          b0c = (tid & 15);
    const int b1r = (tid + 256) >> 4,  b1c = (tid & 15);
    const uint32_t bdst0 = sb + S2_BOFF + b0r * 272 + b0c * 16;
    const uint32_t bdst1 = sb + S2_BOFF + b1r * 272 + b1c * 16;
    const int bcol0 = h0 + b0c * 8, bcol1 = h0 + b1c * 8;

#define S2_ISSUE(s, _bo) do {                                                  \
    int _k0 = (s) * 32;                                                        \
    uint32_t _ad = adst + (_bo);                                               \
    CP16(_ad,      axh + _k0); CP16(_ad + 16, axh + _k0 + 8);                  \
    size_t _g0 = (size_t)(_k0 + b0r) * HH + bcol0;                             \
    size_t _g1 = (size_t)(_k0 + b1r) * HH + bcol1;                             \
    CP16(bdst0 + (_bo), wdh_p + _g0);                                          \
    CP16(bdst1 + (_bo), wdh_p + _g1);                                          \
} while (0)

    uint32_t a_base[2];
#pragma unroll
    for (int i = 0; i < 2; i++)
        a_base[i] = sb + (wm * 32 + i * 16 + (lane & 15)) * 80 + (lane >> 4) * 16;
    const uint32_t b_base = sb + S2_BOFF + (lane & 15) * 272 + (wn * 64 + (lane >> 4) * 8) * 2;

    float acc[2][8][4];
#pragma unroll
    for (int i = 0; i < 2; i++)
#pragma unroll
        for (int j = 0; j < 8; j++)
#pragma unroll
            for (int q = 0; q < 4; q++) acc[i][j][q] = 0.f;

    S2_ISSUE(0, 0u); CPCOMMIT();
    S2_ISSUE(1, S2_BUF); CPCOMMIT();

    uint32_t bo = 0, ibo = 2 * S2_BUF;
    for (int s = 0; s < S2_KLEN / 32; s++) {
        CPWAIT1();
        __syncthreads();
        if (s + 2 < S2_KLEN / 32) S2_ISSUE(s + 2, ibo);
        CPCOMMIT();
#pragma unroll
        for (int kk = 0; kk < 32; kk += 16) {
            uint32_t ah[2][4];
#pragma unroll
            for (int i = 0; i < 2; i++)
                LDSM4(ah[i], a_base[i] + bo + kk * 2);
#pragma unroll
            for (int jq = 0; jq < 2; jq++) {
                uint32_t ba0 = b_base + bo + kk * 272 + jq * 64;
                uint32_t bh0[4], bh1[4];
                LDSM4T(bh0, ba0);
                LDSM4T(bh1, ba0 + 32);
                const int j0 = jq * 4, j1 = jq * 4 + 2;
#pragma unroll
                for (int i = 0; i < 2; i++)
#pragma unroll
                    for (int j2 = 0; j2 < 2; j2++)
                        mma_f16(acc[i][j0 + j2], ah[i], bh0[2 * j2], bh0[2 * j2 + 1]);
#pragma unroll
                for (int i = 0; i < 2; i++)
#pragma unroll
                    for (int j2 = 0; j2 < 2; j2++)
                        mma_f16(acc[i][j1 + j2], ah[i], bh1[2 * j2], bh1[2 * j2 + 1]);
            }
        }
        bo += S2_BUF;  if (bo == 3 * S2_BUF)  bo = 0;
        ibo += S2_BUF; if (ibo == 3 * S2_BUF) ibo = 0;
    }

    // epilogue: weighted partials -> g_part (plain vectorized stores, no atomics)
    const int er = wm * 32 + (lane >> 2);
#pragma unroll
    for (int i = 0; i < 2; i++)
#pragma unroll
        for (int half = 0; half < 2; half++) {
            int rr = er + i * 16 + half * 8;
            if (m0 + rr < cnt) {
                int   id = rid_s[rr];
                float w  = g_wpair[id];
                float* pp = g_part + ((size_t)kc * TT * 2 + id) * HH + h0 + wn * 64 + 2 * (lane & 3);
#pragma unroll
                for (int jp = 0; jp < 4; jp++)
#pragma unroll
                    for (int j2 = 0; j2 < 2; j2++) {
                        int c = jp * 16 + j2 * 8;
                        float2 v = make_float2(w * acc[i][jp * 2 + j2][half * 2 + 0],
                                               w * acc[i][jp * 2 + j2][half * 2 + 1]);
                        *(float2*)(pp + c) = v;
                    }
            }
        }
}

// ---------------- combine: out = sum over {slot, kc}; reset counters for NEXT run ----------------
__global__ __launch_bounds__(256) void combine_kernel(float4* __restrict__ out4) {
    int i = blockIdx.x * blockDim.x + threadIdx.x;
    if (blockIdx.x == 0 && threadIdx.x < EE) g_count[threadIdx.x] = 0;
    int t  = i >> 8;
    int h4 = i & 255;
    const float4* p = (const float4*)g_part;
    size_t r00 = ((size_t)0 * TT * 2 + 2 * t)     * (HH / 4) + h4;
    size_t r01 = ((size_t)0 * TT * 2 + 2 * t + 1) * (HH / 4) + h4;
    size_t r10 = ((size_t)1 * TT * 2 + 2 * t)     * (HH / 4) + h4;
    size_t r11 = ((size_t)1 * TT * 2 + 2 * t + 1) * (HH / 4) + h4;
    float4 a = p[r00], b = p[r01], c = p[r10], d = p[r11];
    out4[i] = make_float4((a.x + b.x) + (c.x + d.x),
                          (a.y + b.y) + (c.y + d.y),
                          (a.z + b.z) + (c.z + d.z),
                          (a.w + b.w) + (c.w + d.w));
}

// ---------------- launch ----------------
extern "C" void kernel_launch(void* const* d_in, const int* in_sizes, int n_in,
                              void* d_out, int out_size) {
    const float* x  = (const float*)d_in[0];
    const float* gw = (const float*)d_in[1];
    const float* wu = (const float*)d_in[2];
    const float* wg = (const float*)d_in[3];
    const float* wd = (const float*)d_in[4];
    float* out = (float*)d_out;

    cudaFuncSetAttribute(stage1_mma, cudaFuncAttributeMaxDynamicSharedMemorySize, SMEM1);
    cudaFuncSetAttribute(stage2_mma, cudaFuncAttributeMaxDynamicSharedMemorySize, SMEM2);

    prep_kernel<<<RB + SPLIT_BLOCKS, 256>>>((const float4*)wu, (const float4*)wg,
                                            (const float4*)wd, (const float4*)x, x, gw);
    stage1_mma<<<dim3(FF / 64, EE * 32), 256, SMEM1>>>();
    stage2_mma<<<dim3((HH / 128) * S2_KC, EE * 32), 256, SMEM2>>>();
    combine_kernel<<<TT * HH / 4 / 256, 256>>>((float4*)out);
}